// round 6
// baseline (speedup 1.0000x reference)
#include <cuda_runtime.h>
#include <cuda_bf16.h>
#include <cstdint>

// Shapes
#define VSZ   32000
#define ESZ   512
#define HSZ   512
#define BSZ   64
#define TSZ   65          // sequence steps
#define G3    1536        // 3*H
#define MROWS (BSZ*TSZ)   // 4160 output rows
#define BH    (BSZ*HSZ)

#define NC    32          // persistent scan CTAs
#define JC    16          // j-columns per CTA
#define WB    520         // bf16 row stride (512+8) -> conflict-free frag loads

// ---------------- device scratch (static allocations only) ----------------
__device__ float          g_HA[2 * BH];
__device__ float          g_HB[2 * BH];
__device__ __nv_bfloat16  g_HAb[2 * BH];
__device__ __nv_bfloat16  g_HBb[2 * BH];
__device__ float          g_GI0[TSZ * BSZ * G3];        // 25.6 MB
__device__ __nv_bfloat16  g_WFCb[(size_t)VSZ * HSZ];    // 32.8 MB
__device__ __nv_bfloat16  g_YSb[(size_t)MROWS * HSZ];   // 4.3 MB
__device__ float          g_SUMEXP[MROWS];
__device__ unsigned       g_cnt;

__device__ __forceinline__ float sigf(float x) { return 1.f / (1.f + __expf(-x)); }

// bf16 mma m16n8k16, fp32 accumulate
__device__ __forceinline__ void mma16816(float* c, const uint32_t* a, uint32_t b0, uint32_t b1)
{
    asm volatile(
        "mma.sync.aligned.m16n8k16.row.col.f32.bf16.bf16.f32 "
        "{%0,%1,%2,%3}, {%4,%5,%6,%7}, {%8,%9}, {%0,%1,%2,%3};\n"
        : "+f"(c[0]), "+f"(c[1]), "+f"(c[2]), "+f"(c[3])
        : "r"(a[0]), "r"(a[1]), "r"(a[2]), "r"(a[3]), "r"(b0), "r"(b1));
}

// grid-wide barrier: RED arrive + LOAD-based (non-RMW) polling
__device__ __forceinline__ void gbar(unsigned target) {
    __syncthreads();
    if (threadIdx.x == 0) {
        unsigned* p = &g_cnt;
        asm volatile("red.release.gpu.global.add.u32 [%0], 1;" :: "l"(p) : "memory");
        unsigned v;
        do {
            asm volatile("ld.acquire.gpu.global.u32 %0, [%1];" : "=r"(v) : "l"(p) : "memory");
        } while (v < target);
    }
    __syncthreads();
}

// ---------------- h0 = tanh(ctx @ W_init^T + b_init); zero SUMEXP,cnt -----
__global__ void k_h0(const float* __restrict__ ctx,
                     const float* __restrict__ W_init,
                     const float* __restrict__ b_init)
{
    const int lb = blockIdx.x;
    const int l = lb >> 6, b = lb & 63;
    const int tid = threadIdx.x;
    __shared__ float cs[HSZ];
    ((float4*)cs)[tid] = ((const float4*)(ctx + (size_t)lb * HSZ))[tid];

    const int gid = blockIdx.x * 128 + tid;
    if (gid < MROWS) g_SUMEXP[gid] = 0.f;
    if (gid == 0) g_cnt = 0;
    __syncthreads();

    float*         hout  = (l == 0) ? g_HA  : g_HB;   // buffer index 0
    __nv_bfloat16* houtb = (l == 0) ? g_HAb : g_HBb;
#pragma unroll
    for (int jj = 0; jj < 4; jj++) {
        const int j = tid * 4 + jj;
        const float* wr = W_init + (size_t)j * HSZ;
        float acc = 0.f;
        for (int k = 0; k < HSZ; k += 4) {
            float4 w = *(const float4*)(wr + k);
            acc += w.x * cs[k] + w.y * cs[k+1] + w.z * cs[k+2] + w.w * cs[k+3];
        }
        float v = tanhf(acc + b_init[j]);
        hout[b * HSZ + j]  = v;
        houtb[b * HSZ + j] = __float2bfloat16(v);
    }
}

// ---------------- W_fc fp32 -> bf16 ---------------------------------------
__global__ void k_cvt_wfc(const float* __restrict__ wfc)
{
    const size_t i = (size_t)blockIdx.x * 256 + threadIdx.x;
    float4 v = ((const float4*)wfc)[i];
    __nv_bfloat162 lo = __floats2bfloat162_rn(v.x, v.y);
    __nv_bfloat162 hi = __floats2bfloat162_rn(v.z, v.w);
    uint2 o; o.x = *(uint32_t*)&lo; o.y = *(uint32_t*)&hi;
    ((uint2*)g_WFCb)[i] = o;
}

// ---------------- GI0[t,b,:] = emb[tok(t,b)] @ Wi0^T + bi0 ----------------
__global__ void k_gi0(const float* __restrict__ emb,
                      const int*   __restrict__ targets,
                      const float* __restrict__ Wi0,
                      const float* __restrict__ bi0)
{
    const int bn = blockIdx.x * 64;
    const int t  = blockIdx.y;
    const int tid = threadIdx.x;
    const int tx = tid & 15, ty = tid >> 4;
    __shared__ float As[64][33];
    __shared__ float Bs[64][33];
    __shared__ int   toks[64];
    if (tid < 64) toks[tid] = (t == 0) ? 1 : targets[tid * TSZ + t - 1];
    __syncthreads();

    float acc[4][4];
#pragma unroll
    for (int i = 0; i < 4; i++)
#pragma unroll
        for (int j = 0; j < 4; j++) acc[i][j] = 0.f;

    for (int k0 = 0; k0 < ESZ; k0 += 32) {
        for (int i = tid; i < 512; i += 256) {
            int r = i >> 3, cg = (i & 7) << 2;
            float4 v = *(const float4*)(emb + (size_t)toks[r] * ESZ + k0 + cg);
            As[r][cg] = v.x; As[r][cg+1] = v.y; As[r][cg+2] = v.z; As[r][cg+3] = v.w;
        }
        for (int i = tid; i < 512; i += 256) {
            int r = i >> 3, cg = (i & 7) << 2;
            float4 v = *(const float4*)(Wi0 + (size_t)(bn + r) * ESZ + k0 + cg);
            Bs[r][cg] = v.x; Bs[r][cg+1] = v.y; Bs[r][cg+2] = v.z; Bs[r][cg+3] = v.w;
        }
        __syncthreads();
#pragma unroll
        for (int k = 0; k < 32; k++) {
            float a[4], bb[4];
#pragma unroll
            for (int i = 0; i < 4; i++) a[i] = As[ty*4+i][k];
#pragma unroll
            for (int j = 0; j < 4; j++) bb[j] = Bs[tx*4+j][k];
#pragma unroll
            for (int i = 0; i < 4; i++)
#pragma unroll
                for (int j = 0; j < 4; j++) acc[i][j] += a[i] * bb[j];
        }
        __syncthreads();
    }
#pragma unroll
    for (int i = 0; i < 4; i++) {
        const int b = ty*4 + i;
#pragma unroll
        for (int j = 0; j < 4; j++) {
            const int n = bn + tx*4 + j;
            g_GI0[((size_t)t * BSZ + b) * G3 + n] = acc[i][j] + bi0[n];
        }
    }
}

// ---------------- persistent fused GRU scan -------------------------------
// 32 CTAs x 256 threads (8 warps). CTA owns 16 j-cols x 3 gates.
// warp: m-tile = wid>>1 (16 rows), j-octet = wid&1 (8 of the 16 cols).
__global__ void __launch_bounds__(256, 1) k_scan(
    const float* __restrict__ Wh0, const float* __restrict__ bh0,
    const float* __restrict__ Wi1, const float* __restrict__ Wh1,
    const float* __restrict__ bi1, const float* __restrict__ bh1)
{
    extern __shared__ __nv_bfloat16 smb[];
    __nv_bfloat16* Wh0s = smb;                 // [48][WB]  (row = gate*16 + jj)
    __nv_bfloat16* Wi1s = smb + 48 * WB;
    __nv_bfloat16* Wh1s = smb + 96 * WB;
    __nv_bfloat16* As_  = smb + 144 * WB;      // [64][WB] shared activation buffer

    const int tid  = threadIdx.x;
    const int wid  = tid >> 5, lane = tid & 31;
    const int g    = lane >> 2, tg = lane & 3;
    const int mt   = wid >> 1;          // m-tile 0..3
    const int hf2  = wid & 1;           // j-octet 0..1
    const int m0   = mt * 16;
    const int jb   = blockIdx.x * JC;

    // ---- load weight slices once (bf16); 48 rows x 512 per matrix ----
    for (int idx = tid; idx < 48 * 128; idx += 256) {
        const int row = idx >> 7, q = idx & 127;     // q = float4 index in row
        const int gate = row >> 4, jj = row & 15;
        const size_t grow = (size_t)(gate * HSZ + jb + jj) * HSZ + q * 4;
        const int o = row * WB + q * 4;
        float4 v0 = *(const float4*)(Wh0 + grow);
        float4 v1 = *(const float4*)(Wi1 + grow);
        float4 v2 = *(const float4*)(Wh1 + grow);
        __nv_bfloat162 p0, p1; uint2 u;
        p0 = __floats2bfloat162_rn(v0.x, v0.y); p1 = __floats2bfloat162_rn(v0.z, v0.w);
        u.x = *(uint32_t*)&p0; u.y = *(uint32_t*)&p1; *(uint2*)(Wh0s + o) = u;
        p0 = __floats2bfloat162_rn(v1.x, v1.y); p1 = __floats2bfloat162_rn(v1.z, v1.w);
        u.x = *(uint32_t*)&p0; u.y = *(uint32_t*)&p1; *(uint2*)(Wi1s + o) = u;
        p0 = __floats2bfloat162_rn(v2.x, v2.y); p1 = __floats2bfloat162_rn(v2.z, v2.w);
        u.x = *(uint32_t*)&p0; u.y = *(uint32_t*)&p1; *(uint2*)(Wh1s + o) = u;
    }
    __syncthreads();

    // ---- preload biases for this thread's 2 j columns ----
    float bg0[3][2], bgi1[3][2], bgh1[3][2];
#pragma unroll
    for (int gi = 0; gi < 3; gi++)
#pragma unroll
        for (int cc = 0; cc < 2; cc++) {
            const int j = gi * HSZ + jb + hf2 * 8 + 2 * tg + cc;
            bg0[gi][cc]  = bh0[j];
            bgi1[gi][cc] = bi1[j];
            bgh1[gi][cc] = bh1[j];
        }

    // stage a 64x512 bf16 matrix from global into As_ (pure copy)
    auto stage = [&](const __nv_bfloat16* src) {
        __syncthreads();                       // WAR: prior mma readers done
#pragma unroll
        for (int i = 0; i < 16; i++) {
            const int idx = i * 256 + tid;
            const int r = idx >> 6, q = idx & 63;
            *(uint4*)(As_ + r * WB + q * 8) =
                __ldcg((const uint4*)(src + (size_t)r * HSZ + q * 8));
        }
        __syncthreads();
    };

    // mma over As_ x W[gate-slice] -> acc[3][4]
    auto mma_block = [&](const __nv_bfloat16* W, float acc[3][4]) {
        const __nv_bfloat16* Ar0 = As_ + (m0 + g) * WB;
        const __nv_bfloat16* Ar1 = Ar0 + 8 * WB;
#pragma unroll
        for (int ks = 0; ks < 32; ks++) {
            const int k = ks * 16;
            uint32_t a[4];
            a[0] = *(const uint32_t*)(Ar0 + k + tg * 2);
            a[1] = *(const uint32_t*)(Ar1 + k + tg * 2);
            a[2] = *(const uint32_t*)(Ar0 + k + 8 + tg * 2);
            a[3] = *(const uint32_t*)(Ar1 + k + 8 + tg * 2);
#pragma unroll
            for (int gi = 0; gi < 3; gi++) {
                const __nv_bfloat16* br = W + (gi * 16 + hf2 * 8 + g) * WB + k + tg * 2;
                mma16816(acc[gi], a, *(const uint32_t*)br, *(const uint32_t*)(br + 8));
            }
        }
    };

    // ================= cell0 =================
    auto do_cell0 = [&](int t) {
        const int cur = t & 1, nxt = cur ^ 1;
        const float* hAin = g_HA + cur * BH;
        float* hAout = g_HA + nxt * BH;
        __nv_bfloat16* hAbout = g_HAb + nxt * BH;

        stage(g_HAb + cur * BH);
        float acc0[3][4];
#pragma unroll
        for (int gi = 0; gi < 3; gi++)
#pragma unroll
            for (int r = 0; r < 4; r++) acc0[gi][r] = 0.f;
        mma_block(Wh0s, acc0);

#pragma unroll
        for (int hfr = 0; hfr < 2; hfr++) {
            const int b = m0 + g + 8 * hfr;
            const float* gi0p = g_GI0 + ((size_t)t * BSZ + b) * G3;
#pragma unroll
            for (int cc = 0; cc < 2; cc++) {
                const int j = jb + hf2 * 8 + 2 * tg + cc;
                const float r = sigf(__ldg(gi0p + j)          + acc0[0][hfr*2+cc] + bg0[0][cc]);
                const float z = sigf(__ldg(gi0p + HSZ + j)    + acc0[1][hfr*2+cc] + bg0[1][cc]);
                const float n = tanhf(__ldg(gi0p + 2*HSZ + j) + r * (acc0[2][hfr*2+cc] + bg0[2][cc]));
                const float hprev = __ldcg(hAin + (size_t)b * HSZ + j);
                const float v = (1.f - z) * n + z * hprev;
                hAout[(size_t)b * HSZ + j]  = v;
                hAbout[(size_t)b * HSZ + j] = __float2bfloat16(v);
            }
        }
    };

    // ================= cell1 =================
    auto do_cell1 = [&](int t) {
        const int cur = t & 1, nxt = cur ^ 1;
        const float* hBin = g_HB + cur * BH;
        float* hBout = g_HB + nxt * BH;
        __nv_bfloat16* hBbout = g_HBb + nxt * BH;

        float accx[3][4], acch[3][4];
#pragma unroll
        for (int gi = 0; gi < 3; gi++)
#pragma unroll
            for (int r = 0; r < 4; r++) { accx[gi][r] = 0.f; acch[gi][r] = 0.f; }

        stage(g_HAb + nxt * BH);     // x = hA(t) output (bf16 mirror)
        mma_block(Wi1s, accx);
        stage(g_HBb + cur * BH);     // h = hB(t-1)
        mma_block(Wh1s, acch);

#pragma unroll
        for (int hfr = 0; hfr < 2; hfr++) {
            const int b = m0 + g + 8 * hfr;
#pragma unroll
            for (int cc = 0; cc < 2; cc++) {
                const int j = jb + hf2 * 8 + 2 * tg + cc;
                const float r = sigf(accx[0][hfr*2+cc] + bgi1[0][cc] + acch[0][hfr*2+cc] + bgh1[0][cc]);
                const float z = sigf(accx[1][hfr*2+cc] + bgi1[1][cc] + acch[1][hfr*2+cc] + bgh1[1][cc]);
                const float n = tanhf(accx[2][hfr*2+cc] + bgi1[2][cc]
                                      + r * (acch[2][hfr*2+cc] + bgh1[2][cc]));
                const float hprev = __ldcg(hBin + (size_t)b * HSZ + j);
                const float v = (1.f - z) * n + z * hprev;
                hBout[(size_t)b * HSZ + j]  = v;
                hBbout[(size_t)b * HSZ + j] = __float2bfloat16(v);
                g_YSb[((size_t)b * TSZ + t) * HSZ + j] = __float2bfloat16(v);
            }
        }
    };

    // ===== phase-grouped schedule: ONE barrier per step =====
    do_cell0(0);
    gbar(NC);
    for (int t = 0; t < TSZ; t++) {
        do_cell1(t);
        if (t < TSZ - 1) {
            do_cell0(t + 1);
            gbar((unsigned)(t + 2) * NC);
        }
    }
}

// ---------------- logits GEMM (bf16 mma) + fused sum-of-exp ---------------
// tile 128(m) x 128(n), 256 threads (2x4 warps, each warp 64m x 32n), BK=64
__global__ void k_logits(const float* __restrict__ b_fc, float* __restrict__ out)
{
    const int bn = blockIdx.x * 128;
    const int bm = blockIdx.y * 128;
    const int tid = threadIdx.x;
    const int wid = tid >> 5, lane = tid & 31;
    const int warp_m = wid >> 2, warp_n = wid & 3;
    const int g = lane >> 2, tg = lane & 3;

    __shared__ __nv_bfloat16 As[128][72];
    __shared__ __nv_bfloat16 Bs[128][72];
    __shared__ float bsm[128];
    __shared__ float ses[128];
    if (tid < 128) { bsm[tid] = b_fc[bn + tid]; ses[tid] = 0.f; }

    float acc[4][4][4];
#pragma unroll
    for (int i = 0; i < 4; i++)
#pragma unroll
        for (int j = 0; j < 4; j++)
#pragma unroll
            for (int r = 0; r < 4; r++) acc[i][j][r] = 0.f;

    for (int k0 = 0; k0 < HSZ; k0 += 64) {
        for (int i = tid; i < 1024; i += 256) {
            int r = i >> 3, q = i & 7;
            int row = bm + r; if (row >= MROWS) row = MROWS - 1;
            *(uint4*)&As[r][q * 8] = *(const uint4*)(g_YSb + (size_t)row * HSZ + k0 + q * 8);
        }
        for (int i = tid; i < 1024; i += 256) {
            int r = i >> 3, q = i & 7;
            *(uint4*)&Bs[r][q * 8] = *(const uint4*)(g_WFCb + (size_t)(bn + r) * HSZ + k0 + q * 8);
        }
        __syncthreads();
#pragma unroll
        for (int kk = 0; kk < 64; kk += 16) {
            uint32_t af[4][4], bfr[4][2];
#pragma unroll
            for (int im = 0; im < 4; im++) {
                int r0 = warp_m * 64 + im * 16;
                af[im][0] = *(const uint32_t*)&As[r0 + g    ][kk + tg*2    ];
                af[im][1] = *(const uint32_t*)&As[r0 + g + 8][kk + tg*2    ];
                af[im][2] = *(const uint32_t*)&As[r0 + g    ][kk + tg*2 + 8];
                af[im][3] = *(const uint32_t*)&As[r0 + g + 8][kk + tg*2 + 8];
            }
#pragma unroll
            for (int in_ = 0; in_ < 4; in_++) {
                int c0 = warp_n * 32 + in_ * 8;
                bfr[in_][0] = *(const uint32_t*)&Bs[c0 + g][kk + tg*2    ];
                bfr[in_][1] = *(const uint32_t*)&Bs[c0 + g][kk + tg*2 + 8];
            }
#pragma unroll
            for (int im = 0; im < 4; im++)
#pragma unroll
                for (int in_ = 0; in_ < 4; in_++)
                    mma16816(acc[im][in_], af[im], bfr[in_][0], bfr[in_][1]);
        }
        __syncthreads();
    }

#pragma unroll
    for (int im = 0; im < 4; im++) {
#pragma unroll
        for (int half = 0; half < 2; half++) {
            const int row_l = warp_m * 64 + im * 16 + g + half * 8;
            const int row = bm + row_l;
            if (row >= MROWS) continue;
            float s = 0.f;
#pragma unroll
            for (int in_ = 0; in_ < 4; in_++) {
                const int col_l = warp_n * 32 + in_ * 8 + tg * 2;
                float v0 = acc[im][in_][half*2 + 0] + bsm[col_l];
                float v1 = acc[im][in_][half*2 + 1] + bsm[col_l + 1];
                float2 st; st.x = v0; st.y = v1;
                *(float2*)(out + (size_t)row * VSZ + bn + col_l) = st;
                s += __expf(v0) + __expf(v1);
            }
            atomicAdd(&ses[row_l], s);
        }
    }
    __syncthreads();
    if (tid < 128 && bm + tid < MROWS) atomicAdd(&g_SUMEXP[bm + tid], ses[tid]);
}

// ---------------- fixup: out -= log(sumexp(row)) ---------------------------
__global__ void k_fix(float* __restrict__ out)
{
    const size_t i = (size_t)blockIdx.x * 256 + threadIdx.x;  // over float4s
    const int row = (int)(i / (VSZ / 4));
    const float l = logf(g_SUMEXP[row]);
    float4 v = ((const float4*)out)[i];
    v.x -= l; v.y -= l; v.z -= l; v.w -= l;
    ((float4*)out)[i] = v;
}

// ---------------- launch ---------------------------------------------------
extern "C" void kernel_launch(void* const* d_in, const int* in_sizes, int n_in,
                              void* d_out, int out_size)
{
    const float* ctx     = (const float*)d_in[0];
    const int*   targets = (const int*)  d_in[1];
    const float* emb     = (const float*)d_in[2];
    const float* W_init  = (const float*)d_in[3];
    const float* b_init  = (const float*)d_in[4];
    const float* Wi0     = (const float*)d_in[5];
    const float* Wh0     = (const float*)d_in[6];
    const float* bi0     = (const float*)d_in[7];
    const float* bh0     = (const float*)d_in[8];
    const float* Wi1     = (const float*)d_in[9];
    const float* Wh1     = (const float*)d_in[10];
    const float* bi1     = (const float*)d_in[11];
    const float* bh1     = (const float*)d_in[12];
    const float* W_fc    = (const float*)d_in[13];
    const float* b_fc    = (const float*)d_in[14];
    float* out = (float*)d_out;

    static int smem_set = 0;
    const int scan_smem = (144 + 64) * WB * 2;   // 216,320 B
    if (!smem_set) {
        cudaFuncSetAttribute(k_scan, cudaFuncAttributeMaxDynamicSharedMemorySize, scan_smem);
        smem_set = 1;
    }

    k_h0<<<128, 128>>>(ctx, W_init, b_init);
    k_cvt_wfc<<<(VSZ * HSZ / 4) / 256, 256>>>(W_fc);
    k_gi0<<<dim3(24, TSZ), 256>>>(emb, targets, Wi0, bi0);

    k_scan<<<NC, 256, scan_smem>>>(Wh0, bh0, Wi1, Wh1, bi1, bh1);

    k_logits<<<dim3(VSZ / 128, (MROWS + 127) / 128), 256>>>(b_fc, out);
    k_fix<<<((size_t)MROWS * VSZ / 4) / 256, 256>>>(out);
}

// round 7
// speedup vs baseline: 1.1384x; 1.1384x over previous
#include <cuda_runtime.h>
#include <cuda_bf16.h>
#include <cstdint>

// Shapes
#define VSZ   32000
#define ESZ   512
#define HSZ   512
#define BSZ   64
#define TSZ   65          // sequence steps
#define G3    1536        // 3*H
#define MROWS (BSZ*TSZ)   // 4160 output rows
#define BH    (BSZ*HSZ)

#define NC    64          // persistent scan CTAs (1 wave)
#define JC    8           // j-columns per CTA
#define WB    520         // bf16 row stride (512+8) -> conflict-free frag loads

// ---------------- device scratch (static allocations only) ----------------
__device__ float          g_HA[2 * BH];
__device__ float          g_HB[2 * BH];
__device__ __nv_bfloat16  g_HAb[2 * BH];
__device__ __nv_bfloat16  g_HBb[2 * BH];
__device__ float          g_GI0[TSZ * BSZ * G3];        // 25.6 MB
__device__ __nv_bfloat16  g_WFCb[(size_t)VSZ * HSZ];    // 32.8 MB
__device__ __nv_bfloat16  g_YSb[(size_t)MROWS * HSZ];   // 4.3 MB
__device__ float          g_SUMEXP[MROWS];
__device__ unsigned       g_cnt;

__device__ __forceinline__ float sigf(float x) { return 1.f / (1.f + __expf(-x)); }

// bf16 mma m16n8k16, fp32 accumulate
__device__ __forceinline__ void mma16816(float* c, const uint32_t* a, uint32_t b0, uint32_t b1)
{
    asm volatile(
        "mma.sync.aligned.m16n8k16.row.col.f32.bf16.bf16.f32 "
        "{%0,%1,%2,%3}, {%4,%5,%6,%7}, {%8,%9}, {%0,%1,%2,%3};\n"
        : "+f"(c[0]), "+f"(c[1]), "+f"(c[2]), "+f"(c[3])
        : "r"(a[0]), "r"(a[1]), "r"(a[2]), "r"(a[3]), "r"(b0), "r"(b1));
}

// grid-wide barrier: RED arrive + LOAD-based (non-RMW) polling
__device__ __forceinline__ void gbar(unsigned target) {
    __syncthreads();
    if (threadIdx.x == 0) {
        unsigned* p = &g_cnt;
        asm volatile("red.release.gpu.global.add.u32 [%0], 1;" :: "l"(p) : "memory");
        unsigned v;
        do {
            asm volatile("ld.acquire.gpu.global.u32 %0, [%1];" : "=r"(v) : "l"(p) : "memory");
        } while (v < target);
    }
    __syncthreads();
}

// ---------------- h0 = tanh(ctx @ W_init^T + b_init); zero SUMEXP,cnt -----
__global__ void k_h0(const float* __restrict__ ctx,
                     const float* __restrict__ W_init,
                     const float* __restrict__ b_init)
{
    const int lb = blockIdx.x;
    const int l = lb >> 6, b = lb & 63;
    const int tid = threadIdx.x;
    __shared__ float cs[HSZ];
    ((float4*)cs)[tid] = ((const float4*)(ctx + (size_t)lb * HSZ))[tid];

    const int gid = blockIdx.x * 128 + tid;
    if (gid < MROWS) g_SUMEXP[gid] = 0.f;
    if (gid == 0) g_cnt = 0;
    __syncthreads();

    float*         hout  = (l == 0) ? g_HA  : g_HB;   // buffer index 0
    __nv_bfloat16* houtb = (l == 0) ? g_HAb : g_HBb;
#pragma unroll
    for (int jj = 0; jj < 4; jj++) {
        const int j = tid * 4 + jj;
        const float* wr = W_init + (size_t)j * HSZ;
        float acc = 0.f;
        for (int k = 0; k < HSZ; k += 4) {
            float4 w = *(const float4*)(wr + k);
            acc += w.x * cs[k] + w.y * cs[k+1] + w.z * cs[k+2] + w.w * cs[k+3];
        }
        float v = tanhf(acc + b_init[j]);
        hout[b * HSZ + j]  = v;
        houtb[b * HSZ + j] = __float2bfloat16(v);
    }
}

// ---------------- W_fc fp32 -> bf16 ---------------------------------------
__global__ void k_cvt_wfc(const float* __restrict__ wfc)
{
    const size_t i = (size_t)blockIdx.x * 256 + threadIdx.x;
    float4 v = ((const float4*)wfc)[i];
    __nv_bfloat162 lo = __floats2bfloat162_rn(v.x, v.y);
    __nv_bfloat162 hi = __floats2bfloat162_rn(v.z, v.w);
    uint2 o; o.x = *(uint32_t*)&lo; o.y = *(uint32_t*)&hi;
    ((uint2*)g_WFCb)[i] = o;
}

// ---------------- GI0[t,b,:] = emb[tok(t,b)] @ Wi0^T + bi0 ----------------
__global__ void k_gi0(const float* __restrict__ emb,
                      const int*   __restrict__ targets,
                      const float* __restrict__ Wi0,
                      const float* __restrict__ bi0)
{
    const int bn = blockIdx.x * 64;
    const int t  = blockIdx.y;
    const int tid = threadIdx.x;
    const int tx = tid & 15, ty = tid >> 4;
    __shared__ float As[64][33];
    __shared__ float Bs[64][33];
    __shared__ int   toks[64];
    if (tid < 64) toks[tid] = (t == 0) ? 1 : targets[tid * TSZ + t - 1];
    __syncthreads();

    float acc[4][4];
#pragma unroll
    for (int i = 0; i < 4; i++)
#pragma unroll
        for (int j = 0; j < 4; j++) acc[i][j] = 0.f;

    for (int k0 = 0; k0 < ESZ; k0 += 32) {
        for (int i = tid; i < 512; i += 256) {
            int r = i >> 3, cg = (i & 7) << 2;
            float4 v = *(const float4*)(emb + (size_t)toks[r] * ESZ + k0 + cg);
            As[r][cg] = v.x; As[r][cg+1] = v.y; As[r][cg+2] = v.z; As[r][cg+3] = v.w;
        }
        for (int i = tid; i < 512; i += 256) {
            int r = i >> 3, cg = (i & 7) << 2;
            float4 v = *(const float4*)(Wi0 + (size_t)(bn + r) * ESZ + k0 + cg);
            Bs[r][cg] = v.x; Bs[r][cg+1] = v.y; Bs[r][cg+2] = v.z; Bs[r][cg+3] = v.w;
        }
        __syncthreads();
#pragma unroll
        for (int k = 0; k < 32; k++) {
            float a[4], bb[4];
#pragma unroll
            for (int i = 0; i < 4; i++) a[i] = As[ty*4+i][k];
#pragma unroll
            for (int j = 0; j < 4; j++) bb[j] = Bs[tx*4+j][k];
#pragma unroll
            for (int i = 0; i < 4; i++)
#pragma unroll
                for (int j = 0; j < 4; j++) acc[i][j] += a[i] * bb[j];
        }
        __syncthreads();
    }
#pragma unroll
    for (int i = 0; i < 4; i++) {
        const int b = ty*4 + i;
#pragma unroll
        for (int j = 0; j < 4; j++) {
            const int n = bn + tx*4 + j;
            g_GI0[((size_t)t * BSZ + b) * G3 + n] = acc[i][j] + bi0[n];
        }
    }
}

// ---------------- persistent fused GRU scan -------------------------------
// 64 CTAs x 128 threads (4 warps). CTA owns j in [8c, 8c+8) for all 3 gates
// of all three recurrent matrices. One stage + one mma + one epilogue +
// one barrier per timestep.
__global__ void __launch_bounds__(128, 1) k_scan(
    const float* __restrict__ Wh0, const float* __restrict__ bh0,
    const float* __restrict__ Wi1, const float* __restrict__ Wh1,
    const float* __restrict__ bi1, const float* __restrict__ bh1)
{
    extern __shared__ __nv_bfloat16 smb[];
    __nv_bfloat16* Wh0s = smb;                 // [24][WB] (row = gate*8 + jj)
    __nv_bfloat16* Wi1s = smb + 24 * WB;
    __nv_bfloat16* Wh1s = smb + 48 * WB;
    __nv_bfloat16* Ax   = smb + 72 * WB;       // [64][WB] hA staging
    __nv_bfloat16* Ah   = Ax  + 64 * WB;       // [64][WB] hB staging

    const int tid  = threadIdx.x;
    const int wid  = tid >> 5, lane = tid & 31;
    const int g    = lane >> 2, tg = lane & 3;
    const int m0   = wid * 16;
    const int jb   = blockIdx.x * JC;

    // ---- load weight slices once (bf16): 24 rows x 512 per matrix ----
    for (int idx = tid; idx < 24 * 128; idx += 128) {
        const int row = idx >> 7, q = idx & 127;     // q = float4 index in row
        const int gate = row >> 3, jj = row & 7;
        const size_t grow = (size_t)(gate * HSZ + jb + jj) * HSZ + q * 4;
        const int o = row * WB + q * 4;
        float4 v0 = *(const float4*)(Wh0 + grow);
        float4 v1 = *(const float4*)(Wi1 + grow);
        float4 v2 = *(const float4*)(Wh1 + grow);
        __nv_bfloat162 p0, p1; uint2 u;
        p0 = __floats2bfloat162_rn(v0.x, v0.y); p1 = __floats2bfloat162_rn(v0.z, v0.w);
        u.x = *(uint32_t*)&p0; u.y = *(uint32_t*)&p1; *(uint2*)(Wh0s + o) = u;
        p0 = __floats2bfloat162_rn(v1.x, v1.y); p1 = __floats2bfloat162_rn(v1.z, v1.w);
        u.x = *(uint32_t*)&p0; u.y = *(uint32_t*)&p1; *(uint2*)(Wi1s + o) = u;
        p0 = __floats2bfloat162_rn(v2.x, v2.y); p1 = __floats2bfloat162_rn(v2.z, v2.w);
        u.x = *(uint32_t*)&p0; u.y = *(uint32_t*)&p1; *(uint2*)(Wh1s + o) = u;
    }
    __syncthreads();

    // ---- preload biases for this thread's 2 j columns ----
    float bg0[3][2], bgi1[3][2], bgh1[3][2];
#pragma unroll
    for (int gi = 0; gi < 3; gi++)
#pragma unroll
        for (int cc = 0; cc < 2; cc++) {
            const int j = gi * HSZ + jb + 2 * tg + cc;
            bg0[gi][cc]  = bh0[j];
            bgi1[gi][cc] = bi1[j];
            bgh1[gi][cc] = bh1[j];
        }

    // ---- epilogue for cell0(step tt): acc -> hA(tt out) ----
    auto epi0 = [&](int tt, const float acc0[3][4]) {
        const float* hAin = g_HA + (tt & 1) * BH;
        float* hAout = g_HA + ((tt & 1) ^ 1) * BH;
        __nv_bfloat16* hAbout = g_HAb + ((tt & 1) ^ 1) * BH;
#pragma unroll
        for (int hf = 0; hf < 2; hf++) {
            const int b = m0 + g + 8 * hf;
            const float* gi0p = g_GI0 + ((size_t)tt * BSZ + b) * G3;
#pragma unroll
            for (int cc = 0; cc < 2; cc++) {
                const int j = jb + 2 * tg + cc;
                const float r = sigf(__ldg(gi0p + j)          + acc0[0][hf*2+cc] + bg0[0][cc]);
                const float z = sigf(__ldg(gi0p + HSZ + j)    + acc0[1][hf*2+cc] + bg0[1][cc]);
                const float n = tanhf(__ldg(gi0p + 2*HSZ + j) + r * (acc0[2][hf*2+cc] + bg0[2][cc]));
                const float hprev = __ldcg(hAin + (size_t)b * HSZ + j);
                const float v = (1.f - z) * n + z * hprev;
                hAout[(size_t)b * HSZ + j]  = v;
                hAbout[(size_t)b * HSZ + j] = __float2bfloat16(v);
            }
        }
    };

    // ================ prologue: cell0(t=0) ================
    {
        // stage hA buf0 (all 4 warps, 16 rows each)
        {
            const __nv_bfloat16* src = g_HAb;   // buffer 0
#pragma unroll
            for (int i = 0; i < 16; i++) {
                const int row = m0 + i;
                *(uint4*)(Ax + row * WB + lane * 8) =
                    __ldcg((const uint4*)(src + (size_t)row * HSZ + lane * 8));
                *(uint4*)(Ax + row * WB + (lane + 32) * 8) =
                    __ldcg((const uint4*)(src + (size_t)row * HSZ + (lane + 32) * 8));
            }
        }
        __syncthreads();
        float acc0[3][4];
#pragma unroll
        for (int gi = 0; gi < 3; gi++)
#pragma unroll
            for (int r = 0; r < 4; r++) acc0[gi][r] = 0.f;
        const __nv_bfloat16* Ar0 = Ax + (m0 + g) * WB;
        const __nv_bfloat16* Ar1 = Ar0 + 8 * WB;
#pragma unroll
        for (int ks = 0; ks < 32; ks++) {
            const int k = ks * 16;
            uint32_t a[4];
            a[0] = *(const uint32_t*)(Ar0 + k + tg * 2);
            a[1] = *(const uint32_t*)(Ar1 + k + tg * 2);
            a[2] = *(const uint32_t*)(Ar0 + k + 8 + tg * 2);
            a[3] = *(const uint32_t*)(Ar1 + k + 8 + tg * 2);
#pragma unroll
            for (int gi = 0; gi < 3; gi++) {
                const __nv_bfloat16* br = Wh0s + (gi * 8 + g) * WB + k + tg * 2;
                mma16816(acc0[gi], a, *(const uint32_t*)br, *(const uint32_t*)(br + 8));
            }
        }
        epi0(0, acc0);
    }
    gbar(NC);

    // ================ main loop: one barrier per step ================
    for (int t = 0; t < TSZ; t++) {
        const int cur = t & 1, nxt = cur ^ 1;

        // ---- stage hA(t) [buf nxt] and hB(t-1) [buf cur] in parallel ----
        __syncthreads();   // WAR vs previous iteration's mma readers
        {
            const __nv_bfloat16* src = (wid < 2) ? (g_HAb + (size_t)nxt * BH)
                                                 : (g_HBb + (size_t)cur * BH);
            __nv_bfloat16* dst = (wid < 2) ? Ax : Ah;
            const int r0 = (wid & 1) * 32;
#pragma unroll
            for (int i = 0; i < 32; i++) {
                const int row = r0 + i;
                *(uint4*)(dst + row * WB + lane * 8) =
                    __ldcg((const uint4*)(src + (size_t)row * HSZ + lane * 8));
                *(uint4*)(dst + row * WB + (lane + 32) * 8) =
                    __ldcg((const uint4*)(src + (size_t)row * HSZ + (lane + 32) * 8));
            }
        }
        __syncthreads();

        // ---- one mma phase: Wi1*hA, Wh0*hA, Wh1*hB ----
        float accx[3][4], acch[3][4], acc0[3][4];
#pragma unroll
        for (int gi = 0; gi < 3; gi++)
#pragma unroll
            for (int r = 0; r < 4; r++) { accx[gi][r]=0.f; acch[gi][r]=0.f; acc0[gi][r]=0.f; }

        const __nv_bfloat16* AxR0 = Ax + (m0 + g) * WB;
        const __nv_bfloat16* AxR1 = AxR0 + 8 * WB;
        const __nv_bfloat16* AhR0 = Ah + (m0 + g) * WB;
        const __nv_bfloat16* AhR1 = AhR0 + 8 * WB;
#pragma unroll
        for (int ks = 0; ks < 32; ks++) {
            const int k = ks * 16;
            uint32_t aA[4], aB[4];
            aA[0] = *(const uint32_t*)(AxR0 + k + tg * 2);
            aA[1] = *(const uint32_t*)(AxR1 + k + tg * 2);
            aA[2] = *(const uint32_t*)(AxR0 + k + 8 + tg * 2);
            aA[3] = *(const uint32_t*)(AxR1 + k + 8 + tg * 2);
            aB[0] = *(const uint32_t*)(AhR0 + k + tg * 2);
            aB[1] = *(const uint32_t*)(AhR1 + k + tg * 2);
            aB[2] = *(const uint32_t*)(AhR0 + k + 8 + tg * 2);
            aB[3] = *(const uint32_t*)(AhR1 + k + 8 + tg * 2);
#pragma unroll
            for (int gi = 0; gi < 3; gi++) {
                const int wrow = (gi * 8 + g) * WB + k + tg * 2;
                const __nv_bfloat16* bi_ = Wi1s + wrow;
                const __nv_bfloat16* b0_ = Wh0s + wrow;
                const __nv_bfloat16* bh_ = Wh1s + wrow;
                mma16816(accx[gi], aA, *(const uint32_t*)bi_, *(const uint32_t*)(bi_ + 8));
                mma16816(acc0[gi], aA, *(const uint32_t*)b0_, *(const uint32_t*)(b0_ + 8));
                mma16816(acch[gi], aB, *(const uint32_t*)bh_, *(const uint32_t*)(bh_ + 8));
            }
        }

        // ---- epilogue cell1: hB(t) ----
        {
            const float* hBin = g_HB + (size_t)cur * BH;
            float* hBout = g_HB + (size_t)nxt * BH;
            __nv_bfloat16* hBbout = g_HBb + (size_t)nxt * BH;
#pragma unroll
            for (int hf = 0; hf < 2; hf++) {
                const int b = m0 + g + 8 * hf;
#pragma unroll
                for (int cc = 0; cc < 2; cc++) {
                    const int j = jb + 2 * tg + cc;
                    const float r = sigf(accx[0][hf*2+cc] + bgi1[0][cc] + acch[0][hf*2+cc] + bgh1[0][cc]);
                    const float z = sigf(accx[1][hf*2+cc] + bgi1[1][cc] + acch[1][hf*2+cc] + bgh1[1][cc]);
                    const float n = tanhf(accx[2][hf*2+cc] + bgi1[2][cc]
                                          + r * (acch[2][hf*2+cc] + bgh1[2][cc]));
                    const float hprev = __ldcg(hBin + (size_t)b * HSZ + j);
                    const float v = (1.f - z) * n + z * hprev;
                    hBout[(size_t)b * HSZ + j]  = v;
                    hBbout[(size_t)b * HSZ + j] = __float2bfloat16(v);
                    g_YSb[((size_t)b * TSZ + t) * HSZ + j] = __float2bfloat16(v);
                }
            }
        }

        // ---- epilogue cell0(t+1): hA(t+1) ----
        if (t < TSZ - 1) {
            epi0(t + 1, acc0);
            gbar((unsigned)(t + 2) * NC);
        }
    }
}

// ---------------- logits GEMM (bf16 mma) + fused sum-of-exp ---------------
// tile 128(m) x 128(n), 256 threads (2x4 warps, each warp 64m x 32n), BK=64
__global__ void k_logits(const float* __restrict__ b_fc, float* __restrict__ out)
{
    const int bn = blockIdx.x * 128;
    const int bm = blockIdx.y * 128;
    const int tid = threadIdx.x;
    const int wid = tid >> 5, lane = tid & 31;
    const int warp_m = wid >> 2, warp_n = wid & 3;
    const int g = lane >> 2, tg = lane & 3;

    __shared__ __nv_bfloat16 As[128][72];
    __shared__ __nv_bfloat16 Bs[128][72];
    __shared__ float bsm[128];
    __shared__ float ses[128];
    if (tid < 128) { bsm[tid] = b_fc[bn + tid]; ses[tid] = 0.f; }

    float acc[4][4][4];
#pragma unroll
    for (int i = 0; i < 4; i++)
#pragma unroll
        for (int j = 0; j < 4; j++)
#pragma unroll
            for (int r = 0; r < 4; r++) acc[i][j][r] = 0.f;

    for (int k0 = 0; k0 < HSZ; k0 += 64) {
        for (int i = tid; i < 1024; i += 256) {
            int r = i >> 3, q = i & 7;
            int row = bm + r; if (row >= MROWS) row = MROWS - 1;
            *(uint4*)&As[r][q * 8] = *(const uint4*)(g_YSb + (size_t)row * HSZ + k0 + q * 8);
        }
        for (int i = tid; i < 1024; i += 256) {
            int r = i >> 3, q = i & 7;
            *(uint4*)&Bs[r][q * 8] = *(const uint4*)(g_WFCb + (size_t)(bn + r) * HSZ + k0 + q * 8);
        }
        __syncthreads();
#pragma unroll
        for (int kk = 0; kk < 64; kk += 16) {
            uint32_t af[4][4], bfr[4][2];
#pragma unroll
            for (int im = 0; im < 4; im++) {
                int r0 = warp_m * 64 + im * 16;
                af[im][0] = *(const uint32_t*)&As[r0 + g    ][kk + tg*2    ];
                af[im][1] = *(const uint32_t*)&As[r0 + g + 8][kk + tg*2    ];
                af[im][2] = *(const uint32_t*)&As[r0 + g    ][kk + tg*2 + 8];
                af[im][3] = *(const uint32_t*)&As[r0 + g + 8][kk + tg*2 + 8];
            }
#pragma unroll
            for (int in_ = 0; in_ < 4; in_++) {
                int c0 = warp_n * 32 + in_ * 8;
                bfr[in_][0] = *(const uint32_t*)&Bs[c0 + g][kk + tg*2    ];
                bfr[in_][1] = *(const uint32_t*)&Bs[c0 + g][kk + tg*2 + 8];
            }
#pragma unroll
            for (int im = 0; im < 4; im++)
#pragma unroll
                for (int in_ = 0; in_ < 4; in_++)
                    mma16816(acc[im][in_], af[im], bfr[in_][0], bfr[in_][1]);
        }
        __syncthreads();
    }

#pragma unroll
    for (int im = 0; im < 4; im++) {
#pragma unroll
        for (int half = 0; half < 2; half++) {
            const int row_l = warp_m * 64 + im * 16 + g + half * 8;
            const int row = bm + row_l;
            if (row >= MROWS) continue;
            float s = 0.f;
#pragma unroll
            for (int in_ = 0; in_ < 4; in_++) {
                const int col_l = warp_n * 32 + in_ * 8 + tg * 2;
                float v0 = acc[im][in_][half*2 + 0] + bsm[col_l];
                float v1 = acc[im][in_][half*2 + 1] + bsm[col_l + 1];
                float2 st; st.x = v0; st.y = v1;
                *(float2*)(out + (size_t)row * VSZ + bn + col_l) = st;
                s += __expf(v0) + __expf(v1);
            }
            atomicAdd(&ses[row_l], s);
        }
    }
    __syncthreads();
    if (tid < 128 && bm + tid < MROWS) atomicAdd(&g_SUMEXP[bm + tid], ses[tid]);
}

// ---------------- fixup: out -= log(sumexp(row)) ---------------------------
__global__ void k_fix(float* __restrict__ out)
{
    const size_t i = (size_t)blockIdx.x * 256 + threadIdx.x;  // over float4s
    const int row = (int)(i / (VSZ / 4));
    const float l = logf(g_SUMEXP[row]);
    float4 v = ((const float4*)out)[i];
    v.x -= l; v.y -= l; v.z -= l; v.w -= l;
    ((float4*)out)[i] = v;
}

// ---------------- launch ---------------------------------------------------
extern "C" void kernel_launch(void* const* d_in, const int* in_sizes, int n_in,
                              void* d_out, int out_size)
{
    const float* ctx     = (const float*)d_in[0];
    const int*   targets = (const int*)  d_in[1];
    const float* emb     = (const float*)d_in[2];
    const float* W_init  = (const float*)d_in[3];
    const float* b_init  = (const float*)d_in[4];
    const float* Wi0     = (const float*)d_in[5];
    const float* Wh0     = (const float*)d_in[6];
    const float* bi0     = (const float*)d_in[7];
    const float* bh0     = (const float*)d_in[8];
    const float* Wi1     = (const float*)d_in[9];
    const float* Wh1     = (const float*)d_in[10];
    const float* bi1     = (const float*)d_in[11];
    const float* bh1     = (const float*)d_in[12];
    const float* W_fc    = (const float*)d_in[13];
    const float* b_fc    = (const float*)d_in[14];
    float* out = (float*)d_out;

    static int smem_set = 0;
    const int scan_smem = (72 + 128) * WB * 2;   // 208,000 B
    if (!smem_set) {
        cudaFuncSetAttribute(k_scan, cudaFuncAttributeMaxDynamicSharedMemorySize, scan_smem);
        smem_set = 1;
    }

    k_h0<<<128, 128>>>(ctx, W_init, b_init);
    k_cvt_wfc<<<(VSZ * HSZ / 4) / 256, 256>>>(W_fc);
    k_gi0<<<dim3(24, TSZ), 256>>>(emb, targets, Wi0, bi0);

    k_scan<<<NC, 128, scan_smem>>>(Wh0, bh0, Wi1, Wh1, bi1, bh1);

    k_logits<<<dim3(VSZ / 128, (MROWS + 127) / 128), 256>>>(b_fc, out);
    k_fix<<<((size_t)MROWS * VSZ / 4) / 256, 256>>>(out);
}

// round 8
// speedup vs baseline: 1.1445x; 1.0054x over previous
#include <cuda_runtime.h>
#include <cuda_bf16.h>
#include <cstdint>

// Shapes
#define VSZ   32000
#define ESZ   512
#define HSZ   512
#define BSZ   64
#define TSZ   65          // sequence steps
#define G3    1536        // 3*H
#define MROWS (BSZ*TSZ)   // 4160 output rows
#define BH    (BSZ*HSZ)

#define NC    64          // persistent scan CTAs (1 wave)
#define JC    8           // j-columns per CTA
#define WB    520         // bf16 row stride (512+8) -> conflict-free frag loads
#define NT    384         // scan threads (12 warps: 4 m-tiles x 3 matrices)

// ---------------- device scratch (static allocations only) ----------------
__device__ float          g_HA[2 * BH];
__device__ float          g_HB[2 * BH];
__device__ __nv_bfloat16  g_HAb[2 * BH];
__device__ __nv_bfloat16  g_HBb[2 * BH];
__device__ float          g_GI0[TSZ * BSZ * G3];        // 25.6 MB
__device__ __nv_bfloat16  g_WFCb[(size_t)VSZ * HSZ];    // 32.8 MB
__device__ __nv_bfloat16  g_YSb[(size_t)MROWS * HSZ];   // 4.3 MB
__device__ float          g_SUMEXP[MROWS];
__device__ unsigned       g_cnt;

__device__ __forceinline__ float sigf(float x) { return 1.f / (1.f + __expf(-x)); }

// bf16 mma m16n8k16, fp32 accumulate
__device__ __forceinline__ void mma16816(float* c, const uint32_t* a, uint32_t b0, uint32_t b1)
{
    asm volatile(
        "mma.sync.aligned.m16n8k16.row.col.f32.bf16.bf16.f32 "
        "{%0,%1,%2,%3}, {%4,%5,%6,%7}, {%8,%9}, {%0,%1,%2,%3};\n"
        : "+f"(c[0]), "+f"(c[1]), "+f"(c[2]), "+f"(c[3])
        : "r"(a[0]), "r"(a[1]), "r"(a[2]), "r"(a[3]), "r"(b0), "r"(b1));
}

// grid-wide barrier: RED arrive + LOAD-based (non-RMW) polling
__device__ __forceinline__ void gbar(unsigned target) {
    __syncthreads();
    if (threadIdx.x == 0) {
        unsigned* p = &g_cnt;
        asm volatile("red.release.gpu.global.add.u32 [%0], 1;" :: "l"(p) : "memory");
        unsigned v;
        do {
            asm volatile("ld.acquire.gpu.global.u32 %0, [%1];" : "=r"(v) : "l"(p) : "memory");
        } while (v < target);
    }
    __syncthreads();
}

// ---------------- h0 = tanh(ctx @ W_init^T + b_init); zero SUMEXP,cnt -----
__global__ void k_h0(const float* __restrict__ ctx,
                     const float* __restrict__ W_init,
                     const float* __restrict__ b_init)
{
    const int lb = blockIdx.x;
    const int l = lb >> 6, b = lb & 63;
    const int tid = threadIdx.x;
    __shared__ float cs[HSZ];
    ((float4*)cs)[tid] = ((const float4*)(ctx + (size_t)lb * HSZ))[tid];

    const int gid = blockIdx.x * 128 + tid;
    if (gid < MROWS) g_SUMEXP[gid] = 0.f;
    if (gid == 0) g_cnt = 0;
    __syncthreads();

    float*         hout  = (l == 0) ? g_HA  : g_HB;   // buffer index 0
    __nv_bfloat16* houtb = (l == 0) ? g_HAb : g_HBb;
#pragma unroll
    for (int jj = 0; jj < 4; jj++) {
        const int j = tid * 4 + jj;
        const float* wr = W_init + (size_t)j * HSZ;
        float acc = 0.f;
        for (int k = 0; k < HSZ; k += 4) {
            float4 w = *(const float4*)(wr + k);
            acc += w.x * cs[k] + w.y * cs[k+1] + w.z * cs[k+2] + w.w * cs[k+3];
        }
        float v = tanhf(acc + b_init[j]);
        hout[b * HSZ + j]  = v;
        houtb[b * HSZ + j] = __float2bfloat16(v);
    }
}

// ---------------- W_fc fp32 -> bf16 ---------------------------------------
__global__ void k_cvt_wfc(const float* __restrict__ wfc)
{
    const size_t i = (size_t)blockIdx.x * 256 + threadIdx.x;
    float4 v = ((const float4*)wfc)[i];
    __nv_bfloat162 lo = __floats2bfloat162_rn(v.x, v.y);
    __nv_bfloat162 hi = __floats2bfloat162_rn(v.z, v.w);
    uint2 o; o.x = *(uint32_t*)&lo; o.y = *(uint32_t*)&hi;
    ((uint2*)g_WFCb)[i] = o;
}

// ---------------- GI0[t,b,:] = emb[tok(t,b)] @ Wi0^T + bi0 ----------------
__global__ void k_gi0(const float* __restrict__ emb,
                      const int*   __restrict__ targets,
                      const float* __restrict__ Wi0,
                      const float* __restrict__ bi0)
{
    const int bn = blockIdx.x * 64;
    const int t  = blockIdx.y;
    const int tid = threadIdx.x;
    const int tx = tid & 15, ty = tid >> 4;
    __shared__ float As[64][33];
    __shared__ float Bs[64][33];
    __shared__ int   toks[64];
    if (tid < 64) toks[tid] = (t == 0) ? 1 : targets[tid * TSZ + t - 1];
    __syncthreads();

    float acc[4][4];
#pragma unroll
    for (int i = 0; i < 4; i++)
#pragma unroll
        for (int j = 0; j < 4; j++) acc[i][j] = 0.f;

    for (int k0 = 0; k0 < ESZ; k0 += 32) {
        for (int i = tid; i < 512; i += 256) {
            int r = i >> 3, cg = (i & 7) << 2;
            float4 v = *(const float4*)(emb + (size_t)toks[r] * ESZ + k0 + cg);
            As[r][cg] = v.x; As[r][cg+1] = v.y; As[r][cg+2] = v.z; As[r][cg+3] = v.w;
        }
        for (int i = tid; i < 512; i += 256) {
            int r = i >> 3, cg = (i & 7) << 2;
            float4 v = *(const float4*)(Wi0 + (size_t)(bn + r) * ESZ + k0 + cg);
            Bs[r][cg] = v.x; Bs[r][cg+1] = v.y; Bs[r][cg+2] = v.z; Bs[r][cg+3] = v.w;
        }
        __syncthreads();
#pragma unroll
        for (int k = 0; k < 32; k++) {
            float a[4], bb[4];
#pragma unroll
            for (int i = 0; i < 4; i++) a[i] = As[ty*4+i][k];
#pragma unroll
            for (int j = 0; j < 4; j++) bb[j] = Bs[tx*4+j][k];
#pragma unroll
            for (int i = 0; i < 4; i++)
#pragma unroll
                for (int j = 0; j < 4; j++) acc[i][j] += a[i] * bb[j];
        }
        __syncthreads();
    }
#pragma unroll
    for (int i = 0; i < 4; i++) {
        const int b = ty*4 + i;
#pragma unroll
        for (int j = 0; j < 4; j++) {
            const int n = bn + tx*4 + j;
            g_GI0[((size_t)t * BSZ + b) * G3 + n] = acc[i][j] + bi0[n];
        }
    }
}

// ---------------- persistent fused GRU scan -------------------------------
// 64 CTAs x 384 threads (12 warps). CTA owns j in [8c, 8c+8) for all 3 gates.
// Warp w: m-tile = w&3, matrix = w>>2 (0=Wi1, 1=Wh0, 2=Wh1).
// Per step: one stage + one (3-way parallel) mma + epilogues + one barrier.
__global__ void __launch_bounds__(NT, 1) k_scan(
    const float* __restrict__ Wh0, const float* __restrict__ bh0,
    const float* __restrict__ Wi1, const float* __restrict__ Wh1,
    const float* __restrict__ bi1, const float* __restrict__ bh1)
{
    extern __shared__ __nv_bfloat16 smb[];
    __nv_bfloat16* Wh0s = smb;                 // [24][WB] (row = gate*8 + jj)
    __nv_bfloat16* Wi1s = smb + 24 * WB;
    __nv_bfloat16* Wh1s = smb + 48 * WB;
    __nv_bfloat16* Ax   = smb + 72 * WB;       // [64][WB] hA staging
    __nv_bfloat16* Ah   = Ax  + 64 * WB;       // [64][WB] hB staging
    float4* accS = (float4*)(smb + 200 * WB);  // [4*3*32] accx scratch (6 KB)

    const int tid  = threadIdx.x;
    const int wid  = tid >> 5, lane = tid & 31;
    const int g    = lane >> 2, tg = lane & 3;
    const int mt   = wid & 3;                  // m-tile 0..3
    const int mat  = wid >> 2;                 // 0=Wi1, 1=Wh0, 2=Wh1
    const int m0   = mt * 16;
    const int jb   = blockIdx.x * JC;

    // ---- load weight slices once (bf16): 24 rows x 512 per matrix ----
    for (int idx = tid; idx < 24 * 128; idx += NT) {
        const int row = idx >> 7, q = idx & 127;     // q = float4 index in row
        const int gate = row >> 3, jj = row & 7;
        const size_t grow = (size_t)(gate * HSZ + jb + jj) * HSZ + q * 4;
        const int o = row * WB + q * 4;
        float4 v0 = *(const float4*)(Wh0 + grow);
        float4 v1 = *(const float4*)(Wi1 + grow);
        float4 v2 = *(const float4*)(Wh1 + grow);
        __nv_bfloat162 p0, p1; uint2 u;
        p0 = __floats2bfloat162_rn(v0.x, v0.y); p1 = __floats2bfloat162_rn(v0.z, v0.w);
        u.x = *(uint32_t*)&p0; u.y = *(uint32_t*)&p1; *(uint2*)(Wh0s + o) = u;
        p0 = __floats2bfloat162_rn(v1.x, v1.y); p1 = __floats2bfloat162_rn(v1.z, v1.w);
        u.x = *(uint32_t*)&p0; u.y = *(uint32_t*)&p1; *(uint2*)(Wi1s + o) = u;
        p0 = __floats2bfloat162_rn(v2.x, v2.y); p1 = __floats2bfloat162_rn(v2.z, v2.w);
        u.x = *(uint32_t*)&p0; u.y = *(uint32_t*)&p1; *(uint2*)(Wh1s + o) = u;
    }
    __syncthreads();

    // ---- preload biases ----
    float bg0[3][2], bgi1[3][2], bgh1[3][2];
#pragma unroll
    for (int gi = 0; gi < 3; gi++)
#pragma unroll
        for (int cc = 0; cc < 2; cc++) {
            const int j = gi * HSZ + jb + 2 * tg + cc;
            bg0[gi][cc]  = bh0[j];
            bgi1[gi][cc] = bi1[j];
            bgh1[gi][cc] = bh1[j];
        }

    // warp-level mma over a staged activation buffer (this warp's m-tile)
    auto mma3 = [&](const __nv_bfloat16* A, const __nv_bfloat16* W, float acc[3][4]) {
        const __nv_bfloat16* Ar0 = A + (m0 + g) * WB;
        const __nv_bfloat16* Ar1 = Ar0 + 8 * WB;
#pragma unroll
        for (int gi = 0; gi < 3; gi++)
#pragma unroll
            for (int r = 0; r < 4; r++) acc[gi][r] = 0.f;
#pragma unroll
        for (int ks = 0; ks < 32; ks++) {
            const int k = ks * 16;
            uint32_t a[4];
            a[0] = *(const uint32_t*)(Ar0 + k + tg * 2);
            a[1] = *(const uint32_t*)(Ar1 + k + tg * 2);
            a[2] = *(const uint32_t*)(Ar0 + k + 8 + tg * 2);
            a[3] = *(const uint32_t*)(Ar1 + k + 8 + tg * 2);
#pragma unroll
            for (int gi = 0; gi < 3; gi++) {
                const __nv_bfloat16* br = W + (gi * 8 + g) * WB + k + tg * 2;
                mma16816(acc[gi], a, *(const uint32_t*)br, *(const uint32_t*)(br + 8));
            }
        }
    };

    // ---- cell0 epilogue for step tt (uses acc0 = Wh0*hA(tt-in)) ----
    auto epi0 = [&](int tt, const float acc0[3][4]) {
        const float* hAin = g_HA + (tt & 1) * BH;
        float* hAout = g_HA + ((tt & 1) ^ 1) * BH;
        __nv_bfloat16* hAbout = g_HAb + ((tt & 1) ^ 1) * BH;
#pragma unroll
        for (int hf = 0; hf < 2; hf++) {
            const int b = m0 + g + 8 * hf;
            const float* gi0p = g_GI0 + ((size_t)tt * BSZ + b) * G3;
#pragma unroll
            for (int cc = 0; cc < 2; cc++) {
                const int j = jb + 2 * tg + cc;
                const float r = sigf(__ldg(gi0p + j)          + acc0[0][hf*2+cc] + bg0[0][cc]);
                const float z = sigf(__ldg(gi0p + HSZ + j)    + acc0[1][hf*2+cc] + bg0[1][cc]);
                const float n = tanhf(__ldg(gi0p + 2*HSZ + j) + r * (acc0[2][hf*2+cc] + bg0[2][cc]));
                const float hprev = __ldcg(hAin + (size_t)b * HSZ + j);
                const float v = (1.f - z) * n + z * hprev;
                hAout[(size_t)b * HSZ + j]  = v;
                hAbout[(size_t)b * HSZ + j] = __float2bfloat16(v);
            }
        }
    };

    // ================ prologue: cell0(t=0) ================
    {
        // stage hA buf0 into Ax (all threads)
        for (int idx = tid; idx < 64 * 64; idx += NT) {
            const int r = idx >> 6, q = idx & 63;
            *(uint4*)(Ax + r * WB + q * 8) =
                __ldcg((const uint4*)(g_HAb + (size_t)r * HSZ + q * 8));
        }
        __syncthreads();
        if (mat == 1) {
            float acc0[3][4];
            mma3(Ax, Wh0s, acc0);
            epi0(0, acc0);
        }
    }
    gbar(NC);

    // ================ main loop: one barrier per step ================
    for (int t = 0; t < TSZ; t++) {
        const int cur = t & 1, nxt = cur ^ 1;

        // ---- stage hA(t) [buf nxt] -> Ax, hB(t-1) [buf cur] -> Ah ----
        {
            const __nv_bfloat16* srcA = g_HAb + (size_t)nxt * BH;
            const __nv_bfloat16* srcB = g_HBb + (size_t)cur * BH;
            for (int idx = tid; idx < 128 * 64; idx += NT) {
                const int r = idx >> 6, q = idx & 63;
                if (r < 64)
                    *(uint4*)(Ax + r * WB + q * 8) =
                        __ldcg((const uint4*)(srcA + (size_t)r * HSZ + q * 8));
                else
                    *(uint4*)(Ah + (r - 64) * WB + q * 8) =
                        __ldcg((const uint4*)(srcB + (size_t)(r - 64) * HSZ + q * 8));
            }
        }
        __syncthreads();

        // ---- 3-way parallel mma ----
        float acc[3][4];
        if (mat == 0)      mma3(Ax, Wi1s, acc);   // accx
        else if (mat == 1) mma3(Ax, Wh0s, acc);   // acc0 (for cell0(t+1))
        else               mma3(Ah, Wh1s, acc);   // acch

        if (mat == 0) {
#pragma unroll
            for (int gi = 0; gi < 3; gi++) {
                float4 v; v.x = acc[gi][0]; v.y = acc[gi][1]; v.z = acc[gi][2]; v.w = acc[gi][3];
                accS[(mt * 3 + gi) * 32 + lane] = v;
            }
        }
        __syncthreads();

        // ---- epilogues ----
        if (mat == 2) {
            // cell1: combine accx (smem) + acch (regs)
            const float* hBin = g_HB + (size_t)cur * BH;
            float* hBout = g_HB + (size_t)nxt * BH;
            __nv_bfloat16* hBbout = g_HBb + (size_t)nxt * BH;
            float accx[3][4];
#pragma unroll
            for (int gi = 0; gi < 3; gi++) {
                float4 v = accS[(mt * 3 + gi) * 32 + lane];
                accx[gi][0] = v.x; accx[gi][1] = v.y; accx[gi][2] = v.z; accx[gi][3] = v.w;
            }
#pragma unroll
            for (int hf = 0; hf < 2; hf++) {
                const int b = m0 + g + 8 * hf;
#pragma unroll
                for (int cc = 0; cc < 2; cc++) {
                    const int j = jb + 2 * tg + cc;
                    const float r = sigf(accx[0][hf*2+cc] + bgi1[0][cc] + acc[0][hf*2+cc] + bgh1[0][cc]);
                    const float z = sigf(accx[1][hf*2+cc] + bgi1[1][cc] + acc[1][hf*2+cc] + bgh1[1][cc]);
                    const float n = tanhf(accx[2][hf*2+cc] + bgi1[2][cc]
                                          + r * (acc[2][hf*2+cc] + bgh1[2][cc]));
                    const float hprev = __ldcg(hBin + (size_t)b * HSZ + j);
                    const float v = (1.f - z) * n + z * hprev;
                    hBout[(size_t)b * HSZ + j]  = v;
                    hBbout[(size_t)b * HSZ + j] = __float2bfloat16(v);
                    g_YSb[((size_t)b * TSZ + t) * HSZ + j] = __float2bfloat16(v);
                }
            }
        } else if (mat == 1 && t < TSZ - 1) {
            epi0(t + 1, acc);
        }

        if (t < TSZ - 1) gbar((unsigned)(t + 2) * NC);
    }
}

// ---------------- logits GEMM (bf16 mma) + fused sum-of-exp ---------------
// tile 128(m) x 128(n), 256 threads (2x4 warps, each warp 64m x 32n), BK=64
__global__ void k_logits(const float* __restrict__ b_fc, float* __restrict__ out)
{
    const int bn = blockIdx.x * 128;
    const int bm = blockIdx.y * 128;
    const int tid = threadIdx.x;
    const int wid = tid >> 5, lane = tid & 31;
    const int warp_m = wid >> 2, warp_n = wid & 3;
    const int g = lane >> 2, tg = lane & 3;

    __shared__ __nv_bfloat16 As[128][72];
    __shared__ __nv_bfloat16 Bs[128][72];
    __shared__ float bsm[128];
    __shared__ float ses[128];
    if (tid < 128) { bsm[tid] = b_fc[bn + tid]; ses[tid] = 0.f; }

    float acc[4][4][4];
#pragma unroll
    for (int i = 0; i < 4; i++)
#pragma unroll
        for (int j = 0; j < 4; j++)
#pragma unroll
            for (int r = 0; r < 4; r++) acc[i][j][r] = 0.f;

    for (int k0 = 0; k0 < HSZ; k0 += 64) {
        for (int i = tid; i < 1024; i += 256) {
            int r = i >> 3, q = i & 7;
            int row = bm + r; if (row >= MROWS) row = MROWS - 1;
            *(uint4*)&As[r][q * 8] = *(const uint4*)(g_YSb + (size_t)row * HSZ + k0 + q * 8);
        }
        for (int i = tid; i < 1024; i += 256) {
            int r = i >> 3, q = i & 7;
            *(uint4*)&Bs[r][q * 8] = *(const uint4*)(g_WFCb + (size_t)(bn + r) * HSZ + k0 + q * 8);
        }
        __syncthreads();
#pragma unroll
        for (int kk = 0; kk < 64; kk += 16) {
            uint32_t af[4][4], bfr[4][2];
#pragma unroll
            for (int im = 0; im < 4; im++) {
                int r0 = warp_m * 64 + im * 16;
                af[im][0] = *(const uint32_t*)&As[r0 + g    ][kk + tg*2    ];
                af[im][1] = *(const uint32_t*)&As[r0 + g + 8][kk + tg*2    ];
                af[im][2] = *(const uint32_t*)&As[r0 + g    ][kk + tg*2 + 8];
                af[im][3] = *(const uint32_t*)&As[r0 + g + 8][kk + tg*2 + 8];
            }
#pragma unroll
            for (int in_ = 0; in_ < 4; in_++) {
                int c0 = warp_n * 32 + in_ * 8;
                bfr[in_][0] = *(const uint32_t*)&Bs[c0 + g][kk + tg*2    ];
                bfr[in_][1] = *(const uint32_t*)&Bs[c0 + g][kk + tg*2 + 8];
            }
#pragma unroll
            for (int im = 0; im < 4; im++)
#pragma unroll
                for (int in_ = 0; in_ < 4; in_++)
                    mma16816(acc[im][in_], af[im], bfr[in_][0], bfr[in_][1]);
        }
        __syncthreads();
    }

#pragma unroll
    for (int im = 0; im < 4; im++) {
#pragma unroll
        for (int half = 0; half < 2; half++) {
            const int row_l = warp_m * 64 + im * 16 + g + half * 8;
            const int row = bm + row_l;
            if (row >= MROWS) continue;
            float s = 0.f;
#pragma unroll
            for (int in_ = 0; in_ < 4; in_++) {
                const int col_l = warp_n * 32 + in_ * 8 + tg * 2;
                float v0 = acc[im][in_][half*2 + 0] + bsm[col_l];
                float v1 = acc[im][in_][half*2 + 1] + bsm[col_l + 1];
                float2 st; st.x = v0; st.y = v1;
                *(float2*)(out + (size_t)row * VSZ + bn + col_l) = st;
                s += __expf(v0) + __expf(v1);
            }
            atomicAdd(&ses[row_l], s);
        }
    }
    __syncthreads();
    if (tid < 128 && bm + tid < MROWS) atomicAdd(&g_SUMEXP[bm + tid], ses[tid]);
}

// ---------------- fixup: out -= log(sumexp(row)) ---------------------------
__global__ void k_fix(float* __restrict__ out)
{
    const size_t i = (size_t)blockIdx.x * 256 + threadIdx.x;  // over float4s
    const int row = (int)(i / (VSZ / 4));
    const float l = logf(g_SUMEXP[row]);
    float4 v = ((const float4*)out)[i];
    v.x -= l; v.y -= l; v.z -= l; v.w -= l;
    ((float4*)out)[i] = v;
}

// ---------------- launch ---------------------------------------------------
extern "C" void kernel_launch(void* const* d_in, const int* in_sizes, int n_in,
                              void* d_out, int out_size)
{
    const float* ctx     = (const float*)d_in[0];
    const int*   targets = (const int*)  d_in[1];
    const float* emb     = (const float*)d_in[2];
    const float* W_init  = (const float*)d_in[3];
    const float* b_init  = (const float*)d_in[4];
    const float* Wi0     = (const float*)d_in[5];
    const float* Wh0     = (const float*)d_in[6];
    const float* bi0     = (const float*)d_in[7];
    const float* bh0     = (const float*)d_in[8];
    const float* Wi1     = (const float*)d_in[9];
    const float* Wh1     = (const float*)d_in[10];
    const float* bi1     = (const float*)d_in[11];
    const float* bh1     = (const float*)d_in[12];
    const float* W_fc    = (const float*)d_in[13];
    const float* b_fc    = (const float*)d_in[14];
    float* out = (float*)d_out;

    static int smem_set = 0;
    const int scan_smem = 200 * WB * 2 + 4 * 3 * 32 * 16;   // 208,000 + 6,144 B
    if (!smem_set) {
        cudaFuncSetAttribute(k_scan, cudaFuncAttributeMaxDynamicSharedMemorySize, scan_smem);
        smem_set = 1;
    }

    k_h0<<<128, 128>>>(ctx, W_init, b_init);
    k_cvt_wfc<<<(VSZ * HSZ / 4) / 256, 256>>>(W_fc);
    k_gi0<<<dim3(24, TSZ), 256>>>(emb, targets, Wi0, bi0);

    k_scan<<<NC, NT, scan_smem>>>(Wh0, bh0, Wi1, Wh1, bi1, bh1);

    k_logits<<<dim3(VSZ / 128, (MROWS + 127) / 128), 256>>>(b_fc, out);
    k_fix<<<((size_t)MROWS * VSZ / 4) / 256, 256>>>(out);
}

// round 9
// speedup vs baseline: 1.1531x; 1.0074x over previous
#include <cuda_runtime.h>
#include <cuda_bf16.h>
#include <cstdint>

// Shapes
#define VSZ   32000
#define ESZ   512
#define HSZ   512
#define BSZ   64
#define TSZ   65          // sequence steps
#define G3    1536        // 3*H
#define MROWS (BSZ*TSZ)   // 4160 output rows
#define BH    (BSZ*HSZ)

#define NC    64          // persistent scan CTAs (1 wave)
#define JC    8           // j-columns per CTA
#define WB    520         // bf16 row stride (512+8) -> conflict-free frag loads
#define NT    384         // scan threads (12 warps: 4 m-tiles x 3 matrices)

// ---------------- device scratch (static allocations only) ----------------
__device__ float          g_HA[2 * BH];
__device__ float          g_HB[2 * BH];
__device__ __nv_bfloat16  g_HAb[2 * BH];
__device__ __nv_bfloat16  g_HBb[2 * BH];
__device__ float          g_GI0[TSZ * BSZ * G3];        // 25.6 MB
__device__ __nv_bfloat16  g_WFCb[(size_t)VSZ * HSZ];    // 32.8 MB
__device__ __nv_bfloat16  g_YSb[(size_t)MROWS * HSZ];   // 4.3 MB
__device__ float          g_SUMEXP[MROWS];
__device__ unsigned       g_flags[NC * 8];              // 32B-strided barrier flags

__device__ __forceinline__ float sigf(float x) { return 1.f / (1.f + __expf(-x)); }

// bf16 mma m16n8k16, fp32 accumulate
__device__ __forceinline__ void mma16816(float* c, const uint32_t* a, uint32_t b0, uint32_t b1)
{
    asm volatile(
        "mma.sync.aligned.m16n8k16.row.col.f32.bf16.bf16.f32 "
        "{%0,%1,%2,%3}, {%4,%5,%6,%7}, {%8,%9}, {%0,%1,%2,%3};\n"
        : "+f"(c[0]), "+f"(c[1]), "+f"(c[2]), "+f"(c[3])
        : "r"(a[0]), "r"(a[1]), "r"(a[2]), "r"(a[3]), "r"(b0), "r"(b1));
}

// grid barrier: per-CTA epoch flags (release-store arrive, lane-parallel acquire poll)
__device__ __forceinline__ void gbar(unsigned epoch, int cta) {
    __syncthreads();
    if (threadIdx.x == 0) {
        asm volatile("st.release.gpu.global.u32 [%0], %1;"
                     :: "l"(g_flags + cta * 8), "r"(epoch) : "memory");
    }
    if (threadIdx.x < 32) {
        const unsigned* p0 = g_flags + threadIdx.x * 8;
        const unsigned* p1 = g_flags + (threadIdx.x + 32) * 8;
        unsigned v0, v1;
        do {
            asm volatile("ld.acquire.gpu.global.u32 %0, [%1];" : "=r"(v0) : "l"(p0) : "memory");
            asm volatile("ld.acquire.gpu.global.u32 %0, [%1];" : "=r"(v1) : "l"(p1) : "memory");
        } while (__any_sync(0xffffffffu, (v0 < epoch) || (v1 < epoch)));
    }
    __syncthreads();
}

// ---------------- h0 = tanh(ctx @ W_init^T + b_init); zero SUMEXP,flags ---
__global__ void k_h0(const float* __restrict__ ctx,
                     const float* __restrict__ W_init,
                     const float* __restrict__ b_init)
{
    const int lb = blockIdx.x;
    const int l = lb >> 6, b = lb & 63;
    const int tid = threadIdx.x;
    __shared__ float cs[HSZ];
    ((float4*)cs)[tid] = ((const float4*)(ctx + (size_t)lb * HSZ))[tid];

    const int gid = blockIdx.x * 128 + tid;
    if (gid < MROWS) g_SUMEXP[gid] = 0.f;
    if (gid < NC * 8) g_flags[gid] = 0;
    __syncthreads();

    float*         hout  = (l == 0) ? g_HA  : g_HB;   // buffer index 0
    __nv_bfloat16* houtb = (l == 0) ? g_HAb : g_HBb;
#pragma unroll
    for (int jj = 0; jj < 4; jj++) {
        const int j = tid * 4 + jj;
        const float* wr = W_init + (size_t)j * HSZ;
        float acc = 0.f;
        for (int k = 0; k < HSZ; k += 4) {
            float4 w = *(const float4*)(wr + k);
            acc += w.x * cs[k] + w.y * cs[k+1] + w.z * cs[k+2] + w.w * cs[k+3];
        }
        float v = tanhf(acc + b_init[j]);
        hout[b * HSZ + j]  = v;
        houtb[b * HSZ + j] = __float2bfloat16(v);
    }
}

// ---------------- W_fc fp32 -> bf16 ---------------------------------------
__global__ void k_cvt_wfc(const float* __restrict__ wfc)
{
    const size_t i = (size_t)blockIdx.x * 256 + threadIdx.x;
    float4 v = ((const float4*)wfc)[i];
    __nv_bfloat162 lo = __floats2bfloat162_rn(v.x, v.y);
    __nv_bfloat162 hi = __floats2bfloat162_rn(v.z, v.w);
    uint2 o; o.x = *(uint32_t*)&lo; o.y = *(uint32_t*)&hi;
    ((uint2*)g_WFCb)[i] = o;
}

// ---------------- GI0 = gather(emb) @ Wi0^T + bi0 (bf16 mma) --------------
// grid (12 n-tiles, 33 m-tiles), 256 threads, tile 128x128, BK=64
__global__ void k_gi0(const float* __restrict__ emb,
                      const int*   __restrict__ targets,
                      const float* __restrict__ Wi0,
                      const float* __restrict__ bi0)
{
    const int bn = blockIdx.x * 128;     // over G3
    const int bm = blockIdx.y * 128;     // over MROWS
    const int tid = threadIdx.x;
    const int wid = tid >> 5, lane = tid & 31;
    const int warp_m = wid >> 2, warp_n = wid & 3;
    const int g = lane >> 2, tg = lane & 3;

    __shared__ __nv_bfloat16 As[128][72];
    __shared__ __nv_bfloat16 Bs[128][72];
    __shared__ float bsm[128];
    __shared__ int   toks[128];
    if (tid < 128) {
        bsm[tid] = bi0[bn + tid];
        int row = bm + tid; if (row >= MROWS) row = MROWS - 1;
        const int t = row >> 6, b = row & 63;
        toks[tid] = (t == 0) ? 1 : targets[b * TSZ + t - 1];
    }
    __syncthreads();

    float acc[4][4][4];
#pragma unroll
    for (int i = 0; i < 4; i++)
#pragma unroll
        for (int j = 0; j < 4; j++)
#pragma unroll
            for (int r = 0; r < 4; r++) acc[i][j][r] = 0.f;

    for (int k0 = 0; k0 < ESZ; k0 += 64) {
        for (int i = tid; i < 2048; i += 256) {       // A: 128 x 64 fp32 -> bf16
            const int r = i >> 4, q = i & 15;
            float4 v = *(const float4*)(emb + (size_t)toks[r] * ESZ + k0 + q * 4);
            __nv_bfloat162 p0 = __floats2bfloat162_rn(v.x, v.y);
            __nv_bfloat162 p1 = __floats2bfloat162_rn(v.z, v.w);
            uint2 u; u.x = *(uint32_t*)&p0; u.y = *(uint32_t*)&p1;
            *(uint2*)&As[r][q * 4] = u;
        }
        for (int i = tid; i < 2048; i += 256) {       // B: Wi0 128 x 64
            const int r = i >> 4, q = i & 15;
            float4 v = *(const float4*)(Wi0 + (size_t)(bn + r) * ESZ + k0 + q * 4);
            __nv_bfloat162 p0 = __floats2bfloat162_rn(v.x, v.y);
            __nv_bfloat162 p1 = __floats2bfloat162_rn(v.z, v.w);
            uint2 u; u.x = *(uint32_t*)&p0; u.y = *(uint32_t*)&p1;
            *(uint2*)&Bs[r][q * 4] = u;
        }
        __syncthreads();
#pragma unroll
        for (int kk = 0; kk < 64; kk += 16) {
            uint32_t af[4][4], bfr[4][2];
#pragma unroll
            for (int im = 0; im < 4; im++) {
                int r0 = warp_m * 64 + im * 16;
                af[im][0] = *(const uint32_t*)&As[r0 + g    ][kk + tg*2    ];
                af[im][1] = *(const uint32_t*)&As[r0 + g + 8][kk + tg*2    ];
                af[im][2] = *(const uint32_t*)&As[r0 + g    ][kk + tg*2 + 8];
                af[im][3] = *(const uint32_t*)&As[r0 + g + 8][kk + tg*2 + 8];
            }
#pragma unroll
            for (int in_ = 0; in_ < 4; in_++) {
                int c0 = warp_n * 32 + in_ * 8;
                bfr[in_][0] = *(const uint32_t*)&Bs[c0 + g][kk + tg*2    ];
                bfr[in_][1] = *(const uint32_t*)&Bs[c0 + g][kk + tg*2 + 8];
            }
#pragma unroll
            for (int im = 0; im < 4; im++)
#pragma unroll
                for (int in_ = 0; in_ < 4; in_++)
                    mma16816(acc[im][in_], af[im], bfr[in_][0], bfr[in_][1]);
        }
        __syncthreads();
    }

#pragma unroll
    for (int im = 0; im < 4; im++) {
#pragma unroll
        for (int half = 0; half < 2; half++) {
            const int row = bm + warp_m * 64 + im * 16 + g + half * 8;
            if (row >= MROWS) continue;
#pragma unroll
            for (int in_ = 0; in_ < 4; in_++) {
                const int col_l = warp_n * 32 + in_ * 8 + tg * 2;
                float2 st;
                st.x = acc[im][in_][half*2 + 0] + bsm[col_l];
                st.y = acc[im][in_][half*2 + 1] + bsm[col_l + 1];
                *(float2*)(g_GI0 + (size_t)row * G3 + bn + col_l) = st;
            }
        }
    }
}

// ---------------- persistent fused GRU scan -------------------------------
// 64 CTAs x 384 threads (12 warps). CTA owns j in [8c, 8c+8) for all 3 gates.
// Warp w: m-tile = w&3, matrix = w>>2 (0=Wi1, 1=Wh0, 2=Wh1).
__global__ void __launch_bounds__(NT, 1) k_scan(
    const float* __restrict__ Wh0, const float* __restrict__ bh0,
    const float* __restrict__ Wi1, const float* __restrict__ Wh1,
    const float* __restrict__ bi1, const float* __restrict__ bh1)
{
    extern __shared__ __nv_bfloat16 smb[];
    __nv_bfloat16* Wh0s = smb;                 // [24][WB] (row = gate*8 + jj)
    __nv_bfloat16* Wi1s = smb + 24 * WB;
    __nv_bfloat16* Wh1s = smb + 48 * WB;
    __nv_bfloat16* Ax   = smb + 72 * WB;       // [64][WB] hA staging
    __nv_bfloat16* Ah   = Ax  + 64 * WB;       // [64][WB] hB staging
    float4* accS = (float4*)(smb + 200 * WB);  // [4*3*32] accx scratch (6 KB)

    const int tid  = threadIdx.x;
    const int wid  = tid >> 5, lane = tid & 31;
    const int g    = lane >> 2, tg = lane & 3;
    const int mt   = wid & 3;                  // m-tile 0..3
    const int mat  = wid >> 2;                 // 0=Wi1, 1=Wh0, 2=Wh1
    const int m0   = mt * 16;
    const int jb   = blockIdx.x * JC;
    const int cta  = blockIdx.x;

    // ---- load weight slices once (bf16): 24 rows x 512 per matrix ----
    for (int idx = tid; idx < 24 * 128; idx += NT) {
        const int row = idx >> 7, q = idx & 127;
        const int gate = row >> 3, jj = row & 7;
        const size_t grow = (size_t)(gate * HSZ + jb + jj) * HSZ + q * 4;
        const int o = row * WB + q * 4;
        float4 v0 = *(const float4*)(Wh0 + grow);
        float4 v1 = *(const float4*)(Wi1 + grow);
        float4 v2 = *(const float4*)(Wh1 + grow);
        __nv_bfloat162 p0, p1; uint2 u;
        p0 = __floats2bfloat162_rn(v0.x, v0.y); p1 = __floats2bfloat162_rn(v0.z, v0.w);
        u.x = *(uint32_t*)&p0; u.y = *(uint32_t*)&p1; *(uint2*)(Wh0s + o) = u;
        p0 = __floats2bfloat162_rn(v1.x, v1.y); p1 = __floats2bfloat162_rn(v1.z, v1.w);
        u.x = *(uint32_t*)&p0; u.y = *(uint32_t*)&p1; *(uint2*)(Wi1s + o) = u;
        p0 = __floats2bfloat162_rn(v2.x, v2.y); p1 = __floats2bfloat162_rn(v2.z, v2.w);
        u.x = *(uint32_t*)&p0; u.y = *(uint32_t*)&p1; *(uint2*)(Wh1s + o) = u;
    }
    __syncthreads();

    // ---- preload biases ----
    float bg0[3][2], bgi1[3][2], bgh1[3][2];
#pragma unroll
    for (int gi = 0; gi < 3; gi++)
#pragma unroll
        for (int cc = 0; cc < 2; cc++) {
            const int j = gi * HSZ + jb + 2 * tg + cc;
            bg0[gi][cc]  = bh0[j];
            bgi1[gi][cc] = bi1[j];
            bgh1[gi][cc] = bh1[j];
        }

    auto mma3 = [&](const __nv_bfloat16* A, const __nv_bfloat16* W, float acc[3][4]) {
        const __nv_bfloat16* Ar0 = A + (m0 + g) * WB;
        const __nv_bfloat16* Ar1 = Ar0 + 8 * WB;
#pragma unroll
        for (int gi = 0; gi < 3; gi++)
#pragma unroll
            for (int r = 0; r < 4; r++) acc[gi][r] = 0.f;
#pragma unroll
        for (int ks = 0; ks < 32; ks++) {
            const int k = ks * 16;
            uint32_t a[4];
            a[0] = *(const uint32_t*)(Ar0 + k + tg * 2);
            a[1] = *(const uint32_t*)(Ar1 + k + tg * 2);
            a[2] = *(const uint32_t*)(Ar0 + k + 8 + tg * 2);
            a[3] = *(const uint32_t*)(Ar1 + k + 8 + tg * 2);
#pragma unroll
            for (int gi = 0; gi < 3; gi++) {
                const __nv_bfloat16* br = W + (gi * 8 + g) * WB + k + tg * 2;
                mma16816(acc[gi], a, *(const uint32_t*)br, *(const uint32_t*)(br + 8));
            }
        }
    };

    auto epi0 = [&](int tt, const float acc0[3][4]) {
        const float* hAin = g_HA + (tt & 1) * BH;
        float* hAout = g_HA + ((tt & 1) ^ 1) * BH;
        __nv_bfloat16* hAbout = g_HAb + ((tt & 1) ^ 1) * BH;
#pragma unroll
        for (int hf = 0; hf < 2; hf++) {
            const int b = m0 + g + 8 * hf;
            const float* gi0p = g_GI0 + ((size_t)tt * BSZ + b) * G3;
#pragma unroll
            for (int cc = 0; cc < 2; cc++) {
                const int j = jb + 2 * tg + cc;
                const float r = sigf(__ldg(gi0p + j)          + acc0[0][hf*2+cc] + bg0[0][cc]);
                const float z = sigf(__ldg(gi0p + HSZ + j)    + acc0[1][hf*2+cc] + bg0[1][cc]);
                const float n = tanhf(__ldg(gi0p + 2*HSZ + j) + r * (acc0[2][hf*2+cc] + bg0[2][cc]));
                const float hprev = __ldcg(hAin + (size_t)b * HSZ + j);
                const float v = (1.f - z) * n + z * hprev;
                hAout[(size_t)b * HSZ + j]  = v;
                hAbout[(size_t)b * HSZ + j] = __float2bfloat16(v);
            }
        }
    };

    // ================ prologue: cell0(t=0) ================
    {
        for (int idx = tid; idx < 64 * 64; idx += NT) {
            const int r = idx >> 6, q = idx & 63;
            *(uint4*)(Ax + r * WB + q * 8) =
                __ldcg((const uint4*)(g_HAb + (size_t)r * HSZ + q * 8));
        }
        __syncthreads();
        if (mat == 1) {
            float acc0[3][4];
            mma3(Ax, Wh0s, acc0);
            epi0(0, acc0);
        }
    }
    gbar(1u, cta);

    // ================ main loop: one barrier per step ================
    for (int t = 0; t < TSZ; t++) {
        const int cur = t & 1, nxt = cur ^ 1;

        // ---- stage hA(t) [buf nxt] -> Ax, hB(t-1) [buf cur] -> Ah ----
        {
            const __nv_bfloat16* srcA = g_HAb + (size_t)nxt * BH;
            const __nv_bfloat16* srcB = g_HBb + (size_t)cur * BH;
            for (int idx = tid; idx < 128 * 64; idx += NT) {
                const int r = idx >> 6, q = idx & 63;
                if (r < 64)
                    *(uint4*)(Ax + r * WB + q * 8) =
                        __ldcg((const uint4*)(srcA + (size_t)r * HSZ + q * 8));
                else
                    *(uint4*)(Ah + (r - 64) * WB + q * 8) =
                        __ldcg((const uint4*)(srcB + (size_t)(r - 64) * HSZ + q * 8));
            }
        }
        __syncthreads();

        // ---- 3-way parallel mma ----
        float acc[3][4];
        if (mat == 0)      mma3(Ax, Wi1s, acc);   // accx
        else if (mat == 1) mma3(Ax, Wh0s, acc);   // acc0 (for cell0(t+1))
        else               mma3(Ah, Wh1s, acc);   // acch

        if (mat == 0) {
#pragma unroll
            for (int gi = 0; gi < 3; gi++) {
                float4 v; v.x = acc[gi][0]; v.y = acc[gi][1]; v.z = acc[gi][2]; v.w = acc[gi][3];
                accS[(mt * 3 + gi) * 32 + lane] = v;
            }
        }
        __syncthreads();

        // ---- epilogues ----
        if (mat == 2) {
            const float* hBin = g_HB + (size_t)cur * BH;
            float* hBout = g_HB + (size_t)nxt * BH;
            __nv_bfloat16* hBbout = g_HBb + (size_t)nxt * BH;
            float accx[3][4];
#pragma unroll
            for (int gi = 0; gi < 3; gi++) {
                float4 v = accS[(mt * 3 + gi) * 32 + lane];
                accx[gi][0] = v.x; accx[gi][1] = v.y; accx[gi][2] = v.z; accx[gi][3] = v.w;
            }
#pragma unroll
            for (int hf = 0; hf < 2; hf++) {
                const int b = m0 + g + 8 * hf;
#pragma unroll
                for (int cc = 0; cc < 2; cc++) {
                    const int j = jb + 2 * tg + cc;
                    const float r = sigf(accx[0][hf*2+cc] + bgi1[0][cc] + acc[0][hf*2+cc] + bgh1[0][cc]);
                    const float z = sigf(accx[1][hf*2+cc] + bgi1[1][cc] + acc[1][hf*2+cc] + bgh1[1][cc]);
                    const float n = tanhf(accx[2][hf*2+cc] + bgi1[2][cc]
                                          + r * (acc[2][hf*2+cc] + bgh1[2][cc]));
                    const float hprev = __ldcg(hBin + (size_t)b * HSZ + j);
                    const float v = (1.f - z) * n + z * hprev;
                    hBout[(size_t)b * HSZ + j]  = v;
                    hBbout[(size_t)b * HSZ + j] = __float2bfloat16(v);
                    g_YSb[((size_t)b * TSZ + t) * HSZ + j] = __float2bfloat16(v);
                }
            }
        } else if (mat == 1 && t < TSZ - 1) {
            epi0(t + 1, acc);
        }

        if (t < TSZ - 1) gbar((unsigned)(t + 2), cta);
    }
}

// ---------------- logits GEMM (bf16 mma) + fused sum-of-exp ---------------
__global__ void k_logits(const float* __restrict__ b_fc, float* __restrict__ out)
{
    const int bn = blockIdx.x * 128;
    const int bm = blockIdx.y * 128;
    const int tid = threadIdx.x;
    const int wid = tid >> 5, lane = tid & 31;
    const int warp_m = wid >> 2, warp_n = wid & 3;
    const int g = lane >> 2, tg = lane & 3;

    __shared__ __nv_bfloat16 As[128][72];
    __shared__ __nv_bfloat16 Bs[128][72];
    __shared__ float bsm[128];
    __shared__ float ses[128];
    if (tid < 128) { bsm[tid] = b_fc[bn + tid]; ses[tid] = 0.f; }

    float acc[4][4][4];
#pragma unroll
    for (int i = 0; i < 4; i++)
#pragma unroll
        for (int j = 0; j < 4; j++)
#pragma unroll
            for (int r = 0; r < 4; r++) acc[i][j][r] = 0.f;

    for (int k0 = 0; k0 < HSZ; k0 += 64) {
        for (int i = tid; i < 1024; i += 256) {
            int r = i >> 3, q = i & 7;
            int row = bm + r; if (row >= MROWS) row = MROWS - 1;
            *(uint4*)&As[r][q * 8] = *(const uint4*)(g_YSb + (size_t)row * HSZ + k0 + q * 8);
        }
        for (int i = tid; i < 1024; i += 256) {
            int r = i >> 3, q = i & 7;
            *(uint4*)&Bs[r][q * 8] = *(const uint4*)(g_WFCb + (size_t)(bn + r) * HSZ + k0 + q * 8);
        }
        __syncthreads();
#pragma unroll
        for (int kk = 0; kk < 64; kk += 16) {
            uint32_t af[4][4], bfr[4][2];
#pragma unroll
            for (int im = 0; im < 4; im++) {
                int r0 = warp_m * 64 + im * 16;
                af[im][0] = *(const uint32_t*)&As[r0 + g    ][kk + tg*2    ];
                af[im][1] = *(const uint32_t*)&As[r0 + g + 8][kk + tg*2    ];
                af[im][2] = *(const uint32_t*)&As[r0 + g    ][kk + tg*2 + 8];
                af[im][3] = *(const uint32_t*)&As[r0 + g + 8][kk + tg*2 + 8];
            }
#pragma unroll
            for (int in_ = 0; in_ < 4; in_++) {
                int c0 = warp_n * 32 + in_ * 8;
                bfr[in_][0] = *(const uint32_t*)&Bs[c0 + g][kk + tg*2    ];
                bfr[in_][1] = *(const uint32_t*)&Bs[c0 + g][kk + tg*2 + 8];
            }
#pragma unroll
            for (int im = 0; im < 4; im++)
#pragma unroll
                for (int in_ = 0; in_ < 4; in_++)
                    mma16816(acc[im][in_], af[im], bfr[in_][0], bfr[in_][1]);
        }
        __syncthreads();
    }

#pragma unroll
    for (int im = 0; im < 4; im++) {
#pragma unroll
        for (int half = 0; half < 2; half++) {
            const int row_l = warp_m * 64 + im * 16 + g + half * 8;
            const int row = bm + row_l;
            if (row >= MROWS) continue;
            float s = 0.f;
#pragma unroll
            for (int in_ = 0; in_ < 4; in_++) {
                const int col_l = warp_n * 32 + in_ * 8 + tg * 2;
                float v0 = acc[im][in_][half*2 + 0] + bsm[col_l];
                float v1 = acc[im][in_][half*2 + 1] + bsm[col_l + 1];
                float2 st; st.x = v0; st.y = v1;
                *(float2*)(out + (size_t)row * VSZ + bn + col_l) = st;
                s += __expf(v0) + __expf(v1);
            }
            atomicAdd(&ses[row_l], s);
        }
    }
    __syncthreads();
    if (tid < 128 && bm + tid < MROWS) atomicAdd(&g_SUMEXP[bm + tid], ses[tid]);
}

// ---------------- fixup: out -= log(sumexp(row)), 4 float4/thread ---------
__global__ void k_fix(float* __restrict__ out)
{
    const size_t base = (size_t)blockIdx.x * 1024 + threadIdx.x;
#pragma unroll
    for (int it = 0; it < 4; it++) {
        const size_t i = base + it * 256;
        const int row = (int)(i / (VSZ / 4));
        const float l = __logf(g_SUMEXP[row]);
        float4 v = ((const float4*)out)[i];
        v.x -= l; v.y -= l; v.z -= l; v.w -= l;
        ((float4*)out)[i] = v;
    }
}

// ---------------- launch ---------------------------------------------------
extern "C" void kernel_launch(void* const* d_in, const int* in_sizes, int n_in,
                              void* d_out, int out_size)
{
    const float* ctx     = (const float*)d_in[0];
    const int*   targets = (const int*)  d_in[1];
    const float* emb     = (const float*)d_in[2];
    const float* W_init  = (const float*)d_in[3];
    const float* b_init  = (const float*)d_in[4];
    const float* Wi0     = (const float*)d_in[5];
    const float* Wh0     = (const float*)d_in[6];
    const float* bi0     = (const float*)d_in[7];
    const float* bh0     = (const float*)d_in[8];
    const float* Wi1     = (const float*)d_in[9];
    const float* Wh1     = (const float*)d_in[10];
    const float* bi1     = (const float*)d_in[11];
    const float* bh1     = (const float*)d_in[12];
    const float* W_fc    = (const float*)d_in[13];
    const float* b_fc    = (const float*)d_in[14];
    float* out = (float*)d_out;

    static int smem_set = 0;
    const int scan_smem = 200 * WB * 2 + 4 * 3 * 32 * 16;   // 208,000 + 6,144 B
    if (!smem_set) {
        cudaFuncSetAttribute(k_scan, cudaFuncAttributeMaxDynamicSharedMemorySize, scan_smem);
        smem_set = 1;
    }

    k_h0<<<128, 128>>>(ctx, W_init, b_init);
    k_cvt_wfc<<<(VSZ * HSZ / 4) / 256, 256>>>(W_fc);
    k_gi0<<<dim3(G3 / 128, (MROWS + 127) / 128), 256>>>(emb, targets, Wi0, bi0);

    k_scan<<<NC, NT, scan_smem>>>(Wh0, bh0, Wi1, Wh1, bi1, bh1);

    k_logits<<<dim3(VSZ / 128, (MROWS + 127) / 128), 256>>>(b_fc, out);
    k_fix<<<(int)(((size_t)MROWS * VSZ / 4) / 1024), 256>>>(out);
}

// round 11
// speedup vs baseline: 1.2549x; 1.0883x over previous
#include <cuda_runtime.h>
#include <cuda_bf16.h>
#include <cstdint>

// Shapes
#define VSZ   32000
#define ESZ   512
#define HSZ   512
#define BSZ   64
#define TSZ   65          // sequence steps
#define G3    1536        // 3*H
#define MROWS (BSZ*TSZ)   // 4160 output rows
#define BH    (BSZ*HSZ)

#define NC    64          // persistent scan CTAs (1 wave)
#define JC    8           // j-columns per CTA
#define WB    520         // bf16 row stride (512+8) -> conflict-free frag loads
#define NT    384         // scan threads (12 warps: 4 m-tiles x 3 matrices)

// ---------------- device scratch (static allocations only) ----------------
__device__ float          g_HA[2 * BH];
__device__ float          g_HB[2 * BH];
__device__ __nv_bfloat16  g_HAb[2 * BH];
__device__ __nv_bfloat16  g_HBb[2 * BH];
__device__ float          g_GI0[TSZ * BSZ * G3];        // 25.6 MB
__device__ __nv_bfloat16  g_WFCb[(size_t)VSZ * HSZ];    // 32.8 MB
__device__ __nv_bfloat16  g_YSb[(size_t)MROWS * HSZ];   // 4.3 MB
__device__ float          g_SUMEXP[MROWS];
__device__ unsigned       g_cnt;

__device__ __forceinline__ float sigf(float x) { return 1.f / (1.f + __expf(-x)); }

// bf16 mma m16n8k16, fp32 accumulate
__device__ __forceinline__ void mma16816(float* c, const uint32_t* a, uint32_t b0, uint32_t b1)
{
    asm volatile(
        "mma.sync.aligned.m16n8k16.row.col.f32.bf16.bf16.f32 "
        "{%0,%1,%2,%3}, {%4,%5,%6,%7}, {%8,%9}, {%0,%1,%2,%3};\n"
        : "+f"(c[0]), "+f"(c[1]), "+f"(c[2]), "+f"(c[3])
        : "r"(a[0]), "r"(a[1]), "r"(a[2]), "r"(a[3]), "r"(b0), "r"(b1));
}

// grid-wide barrier: RED arrive + LOAD-based (non-RMW) polling  (R8 version)
__device__ __forceinline__ void gbar(unsigned target) {
    __syncthreads();
    if (threadIdx.x == 0) {
        unsigned* p = &g_cnt;
        asm volatile("red.release.gpu.global.add.u32 [%0], 1;" :: "l"(p) : "memory");
        unsigned v;
        do {
            asm volatile("ld.acquire.gpu.global.u32 %0, [%1];" : "=r"(v) : "l"(p) : "memory");
        } while (v < target);
    }
    __syncthreads();
}

// cp.async helpers
#define CPA16(d, s) asm volatile("cp.async.cg.shared.global [%0], [%1], 16;" :: "r"(d), "l"(s) : "memory")
#define CPC()       asm volatile("cp.async.commit_group;" ::: "memory")
#define CPW(n)      asm volatile("cp.async.wait_group %0;" :: "n"(n) : "memory")

// ---------------- h0 = tanh(ctx @ W_init^T + b_init); zero SUMEXP,cnt -----
__global__ void k_h0(const float* __restrict__ ctx,
                     const float* __restrict__ W_init,
                     const float* __restrict__ b_init)
{
    const int lb = blockIdx.x;
    const int l = lb >> 6, b = lb & 63;
    const int tid = threadIdx.x;
    __shared__ float cs[HSZ];
    ((float4*)cs)[tid] = ((const float4*)(ctx + (size_t)lb * HSZ))[tid];

    const int gid = blockIdx.x * 128 + tid;
    if (gid < MROWS) g_SUMEXP[gid] = 0.f;
    if (gid == 0) g_cnt = 0;
    __syncthreads();

    float*         hout  = (l == 0) ? g_HA  : g_HB;   // buffer index 0
    __nv_bfloat16* houtb = (l == 0) ? g_HAb : g_HBb;
#pragma unroll
    for (int jj = 0; jj < 4; jj++) {
        const int j = tid * 4 + jj;
        const float* wr = W_init + (size_t)j * HSZ;
        float acc = 0.f;
        for (int k = 0; k < HSZ; k += 4) {
            float4 w = *(const float4*)(wr + k);
            acc += w.x * cs[k] + w.y * cs[k+1] + w.z * cs[k+2] + w.w * cs[k+3];
        }
        float v = tanhf(acc + b_init[j]);
        hout[b * HSZ + j]  = v;
        houtb[b * HSZ + j] = __float2bfloat16(v);
    }
}

// ---------------- W_fc fp32 -> bf16 ---------------------------------------
__global__ void k_cvt_wfc(const float* __restrict__ wfc)
{
    const size_t i = (size_t)blockIdx.x * 256 + threadIdx.x;
    float4 v = ((const float4*)wfc)[i];
    __nv_bfloat162 lo = __floats2bfloat162_rn(v.x, v.y);
    __nv_bfloat162 hi = __floats2bfloat162_rn(v.z, v.w);
    uint2 o; o.x = *(uint32_t*)&lo; o.y = *(uint32_t*)&hi;
    ((uint2*)g_WFCb)[i] = o;
}

// ---------------- GI0 = gather(emb) @ Wi0^T + bi0 (bf16 mma) --------------
__global__ void k_gi0(const float* __restrict__ emb,
                      const int*   __restrict__ targets,
                      const float* __restrict__ Wi0,
                      const float* __restrict__ bi0)
{
    const int bn = blockIdx.x * 128;     // over G3
    const int bm = blockIdx.y * 128;     // over MROWS
    const int tid = threadIdx.x;
    const int wid = tid >> 5, lane = tid & 31;
    const int warp_m = wid >> 2, warp_n = wid & 3;
    const int g = lane >> 2, tg = lane & 3;

    __shared__ __nv_bfloat16 As[128][72];
    __shared__ __nv_bfloat16 Bs[128][72];
    __shared__ float bsm[128];
    __shared__ int   toks[128];
    if (tid < 128) {
        bsm[tid] = bi0[bn + tid];
        int row = bm + tid; if (row >= MROWS) row = MROWS - 1;
        const int t = row >> 6, b = row & 63;
        toks[tid] = (t == 0) ? 1 : targets[b * TSZ + t - 1];
    }
    __syncthreads();

    float acc[4][4][4];
#pragma unroll
    for (int i = 0; i < 4; i++)
#pragma unroll
        for (int j = 0; j < 4; j++)
#pragma unroll
            for (int r = 0; r < 4; r++) acc[i][j][r] = 0.f;

    for (int k0 = 0; k0 < ESZ; k0 += 64) {
        for (int i = tid; i < 2048; i += 256) {
            const int r = i >> 4, q = i & 15;
            float4 v = *(const float4*)(emb + (size_t)toks[r] * ESZ + k0 + q * 4);
            __nv_bfloat162 p0 = __floats2bfloat162_rn(v.x, v.y);
            __nv_bfloat162 p1 = __floats2bfloat162_rn(v.z, v.w);
            uint2 u; u.x = *(uint32_t*)&p0; u.y = *(uint32_t*)&p1;
            *(uint2*)&As[r][q * 4] = u;
        }
        for (int i = tid; i < 2048; i += 256) {
            const int r = i >> 4, q = i & 15;
            float4 v = *(const float4*)(Wi0 + (size_t)(bn + r) * ESZ + k0 + q * 4);
            __nv_bfloat162 p0 = __floats2bfloat162_rn(v.x, v.y);
            __nv_bfloat162 p1 = __floats2bfloat162_rn(v.z, v.w);
            uint2 u; u.x = *(uint32_t*)&p0; u.y = *(uint32_t*)&p1;
            *(uint2*)&Bs[r][q * 4] = u;
        }
        __syncthreads();
#pragma unroll
        for (int kk = 0; kk < 64; kk += 16) {
            uint32_t af[4][4], bfr[4][2];
#pragma unroll
            for (int im = 0; im < 4; im++) {
                int r0 = warp_m * 64 + im * 16;
                af[im][0] = *(const uint32_t*)&As[r0 + g    ][kk + tg*2    ];
                af[im][1] = *(const uint32_t*)&As[r0 + g + 8][kk + tg*2    ];
                af[im][2] = *(const uint32_t*)&As[r0 + g    ][kk + tg*2 + 8];
                af[im][3] = *(const uint32_t*)&As[r0 + g + 8][kk + tg*2 + 8];
            }
#pragma unroll
            for (int in_ = 0; in_ < 4; in_++) {
                int c0 = warp_n * 32 + in_ * 8;
                bfr[in_][0] = *(const uint32_t*)&Bs[c0 + g][kk + tg*2    ];
                bfr[in_][1] = *(const uint32_t*)&Bs[c0 + g][kk + tg*2 + 8];
            }
#pragma unroll
            for (int im = 0; im < 4; im++)
#pragma unroll
                for (int in_ = 0; in_ < 4; in_++)
                    mma16816(acc[im][in_], af[im], bfr[in_][0], bfr[in_][1]);
        }
        __syncthreads();
    }

#pragma unroll
    for (int im = 0; im < 4; im++) {
#pragma unroll
        for (int half = 0; half < 2; half++) {
            const int row = bm + warp_m * 64 + im * 16 + g + half * 8;
            if (row >= MROWS) continue;
#pragma unroll
            for (int in_ = 0; in_ < 4; in_++) {
                const int col_l = warp_n * 32 + in_ * 8 + tg * 2;
                float2 st;
                st.x = acc[im][in_][half*2 + 0] + bsm[col_l];
                st.y = acc[im][in_][half*2 + 1] + bsm[col_l + 1];
                *(float2*)(g_GI0 + (size_t)row * G3 + bn + col_l) = st;
            }
        }
    }
}

// ---------------- persistent fused GRU scan (R8 structure) ----------------
__global__ void __launch_bounds__(NT, 1) k_scan(
    const float* __restrict__ Wh0, const float* __restrict__ bh0,
    const float* __restrict__ Wi1, const float* __restrict__ Wh1,
    const float* __restrict__ bi1, const float* __restrict__ bh1)
{
    extern __shared__ __nv_bfloat16 smb[];
    __nv_bfloat16* Wh0s = smb;                 // [24][WB] (row = gate*8 + jj)
    __nv_bfloat16* Wi1s = smb + 24 * WB;
    __nv_bfloat16* Wh1s = smb + 48 * WB;
    __nv_bfloat16* Ax   = smb + 72 * WB;       // [64][WB] hA staging
    __nv_bfloat16* Ah   = Ax  + 64 * WB;       // [64][WB] hB staging
    float4* accS = (float4*)(smb + 200 * WB);  // [4*3*32] accx scratch (6 KB)

    const int tid  = threadIdx.x;
    const int wid  = tid >> 5, lane = tid & 31;
    const int g    = lane >> 2, tg = lane & 3;
    const int mt   = wid & 3;                  // m-tile 0..3
    const int mat  = wid >> 2;                 // 0=Wi1, 1=Wh0, 2=Wh1
    const int m0   = mt * 16;
    const int jb   = blockIdx.x * JC;

    for (int idx = tid; idx < 24 * 128; idx += NT) {
        const int row = idx >> 7, q = idx & 127;
        const int gate = row >> 3, jj = row & 7;
        const size_t grow = (size_t)(gate * HSZ + jb + jj) * HSZ + q * 4;
        const int o = row * WB + q * 4;
        float4 v0 = *(const float4*)(Wh0 + grow);
        float4 v1 = *(const float4*)(Wi1 + grow);
        float4 v2 = *(const float4*)(Wh1 + grow);
        __nv_bfloat162 p0, p1; uint2 u;
        p0 = __floats2bfloat162_rn(v0.x, v0.y); p1 = __floats2bfloat162_rn(v0.z, v0.w);
        u.x = *(uint32_t*)&p0; u.y = *(uint32_t*)&p1; *(uint2*)(Wh0s + o) = u;
        p0 = __floats2bfloat162_rn(v1.x, v1.y); p1 = __floats2bfloat162_rn(v1.z, v1.w);
        u.x = *(uint32_t*)&p0; u.y = *(uint32_t*)&p1; *(uint2*)(Wi1s + o) = u;
        p0 = __floats2bfloat162_rn(v2.x, v2.y); p1 = __floats2bfloat162_rn(v2.z, v2.w);
        u.x = *(uint32_t*)&p0; u.y = *(uint32_t*)&p1; *(uint2*)(Wh1s + o) = u;
    }
    __syncthreads();

    float bg0[3][2], bgi1[3][2], bgh1[3][2];
#pragma unroll
    for (int gi = 0; gi < 3; gi++)
#pragma unroll
        for (int cc = 0; cc < 2; cc++) {
            const int j = gi * HSZ + jb + 2 * tg + cc;
            bg0[gi][cc]  = bh0[j];
            bgi1[gi][cc] = bi1[j];
            bgh1[gi][cc] = bh1[j];
        }

    auto mma3 = [&](const __nv_bfloat16* A, const __nv_bfloat16* W, float acc[3][4]) {
        const __nv_bfloat16* Ar0 = A + (m0 + g) * WB;
        const __nv_bfloat16* Ar1 = Ar0 + 8 * WB;
#pragma unroll
        for (int gi = 0; gi < 3; gi++)
#pragma unroll
            for (int r = 0; r < 4; r++) acc[gi][r] = 0.f;
#pragma unroll
        for (int ks = 0; ks < 32; ks++) {
            const int k = ks * 16;
            uint32_t a[4];
            a[0] = *(const uint32_t*)(Ar0 + k + tg * 2);
            a[1] = *(const uint32_t*)(Ar1 + k + tg * 2);
            a[2] = *(const uint32_t*)(Ar0 + k + 8 + tg * 2);
            a[3] = *(const uint32_t*)(Ar1 + k + 8 + tg * 2);
#pragma unroll
            for (int gi = 0; gi < 3; gi++) {
                const __nv_bfloat16* br = W + (gi * 8 + g) * WB + k + tg * 2;
                mma16816(acc[gi], a, *(const uint32_t*)br, *(const uint32_t*)(br + 8));
            }
        }
    };

    auto epi0 = [&](int tt, const float acc0[3][4]) {
        const float* hAin = g_HA + (tt & 1) * BH;
        float* hAout = g_HA + ((tt & 1) ^ 1) * BH;
        __nv_bfloat16* hAbout = g_HAb + ((tt & 1) ^ 1) * BH;
#pragma unroll
        for (int hf = 0; hf < 2; hf++) {
            const int b = m0 + g + 8 * hf;
            const float* gi0p = g_GI0 + ((size_t)tt * BSZ + b) * G3;
#pragma unroll
            for (int cc = 0; cc < 2; cc++) {
                const int j = jb + 2 * tg + cc;
                const float r = sigf(__ldg(gi0p + j)          + acc0[0][hf*2+cc] + bg0[0][cc]);
                const float z = sigf(__ldg(gi0p + HSZ + j)    + acc0[1][hf*2+cc] + bg0[1][cc]);
                const float n = tanhf(__ldg(gi0p + 2*HSZ + j) + r * (acc0[2][hf*2+cc] + bg0[2][cc]));
                const float hprev = __ldcg(hAin + (size_t)b * HSZ + j);
                const float v = (1.f - z) * n + z * hprev;
                hAout[(size_t)b * HSZ + j]  = v;
                hAbout[(size_t)b * HSZ + j] = __float2bfloat16(v);
            }
        }
    };

    // prologue: cell0(t=0)
    {
        for (int idx = tid; idx < 64 * 64; idx += NT) {
            const int r = idx >> 6, q = idx & 63;
            *(uint4*)(Ax + r * WB + q * 8) =
                __ldcg((const uint4*)(g_HAb + (size_t)r * HSZ + q * 8));
        }
        __syncthreads();
        if (mat == 1) {
            float acc0[3][4];
            mma3(Ax, Wh0s, acc0);
            epi0(0, acc0);
        }
    }
    gbar(NC);

    for (int t = 0; t < TSZ; t++) {
        const int cur = t & 1, nxt = cur ^ 1;

        {
            const __nv_bfloat16* srcA = g_HAb + (size_t)nxt * BH;
            const __nv_bfloat16* srcB = g_HBb + (size_t)cur * BH;
            for (int idx = tid; idx < 128 * 64; idx += NT) {
                const int r = idx >> 6, q = idx & 63;
                if (r < 64)
                    *(uint4*)(Ax + r * WB + q * 8) =
                        __ldcg((const uint4*)(srcA + (size_t)r * HSZ + q * 8));
                else
                    *(uint4*)(Ah + (r - 64) * WB + q * 8) =
                        __ldcg((const uint4*)(srcB + (size_t)(r - 64) * HSZ + q * 8));
            }
        }
        __syncthreads();

        float acc[3][4];
        if (mat == 0)      mma3(Ax, Wi1s, acc);
        else if (mat == 1) mma3(Ax, Wh0s, acc);
        else               mma3(Ah, Wh1s, acc);

        if (mat == 0) {
#pragma unroll
            for (int gi = 0; gi < 3; gi++) {
                float4 v; v.x = acc[gi][0]; v.y = acc[gi][1]; v.z = acc[gi][2]; v.w = acc[gi][3];
                accS[(mt * 3 + gi) * 32 + lane] = v;
            }
        }
        __syncthreads();

        if (mat == 2) {
            const float* hBin = g_HB + (size_t)cur * BH;
            float* hBout = g_HB + (size_t)nxt * BH;
            __nv_bfloat16* hBbout = g_HBb + (size_t)nxt * BH;
            float accx[3][4];
#pragma unroll
            for (int gi = 0; gi < 3; gi++) {
                float4 v = accS[(mt * 3 + gi) * 32 + lane];
                accx[gi][0] = v.x; accx[gi][1] = v.y; accx[gi][2] = v.z; accx[gi][3] = v.w;
            }
#pragma unroll
            for (int hf = 0; hf < 2; hf++) {
                const int b = m0 + g + 8 * hf;
#pragma unroll
                for (int cc = 0; cc < 2; cc++) {
                    const int j = jb + 2 * tg + cc;
                    const float r = sigf(accx[0][hf*2+cc] + bgi1[0][cc] + acc[0][hf*2+cc] + bgh1[0][cc]);
                    const float z = sigf(accx[1][hf*2+cc] + bgi1[1][cc] + acc[1][hf*2+cc] + bgh1[1][cc]);
                    const float n = tanhf(accx[2][hf*2+cc] + bgi1[2][cc]
                                          + r * (acc[2][hf*2+cc] + bgh1[2][cc]));
                    const float hprev = __ldcg(hBin + (size_t)b * HSZ + j);
                    const float v = (1.f - z) * n + z * hprev;
                    hBout[(size_t)b * HSZ + j]  = v;
                    hBbout[(size_t)b * HSZ + j] = __float2bfloat16(v);
                    g_YSb[((size_t)b * TSZ + t) * HSZ + j] = __float2bfloat16(v);
                }
            }
        } else if (mat == 1 && t < TSZ - 1) {
            epi0(t + 1, acc);
        }

        if (t < TSZ - 1) gbar((unsigned)(t + 2) * NC);
    }
}

// ---------------- logits GEMM (bf16 mma, cp.async 2-stage) + sum-of-exp ---
// tile 128m x 128n, 256 threads (2x4 warps), BK=64, double-buffered smem
#define LG_STRIDE 72
#define LG_BUF    (128 * LG_STRIDE)                 // one stage of A or B
#define LG_SMEM   (4 * LG_BUF * 2)                  // 2 stages x (A+B) x bf16
__global__ void __launch_bounds__(256, 1) k_logits(const float* __restrict__ b_fc,
                                                   float* __restrict__ out)
{
    extern __shared__ __nv_bfloat16 sm_[];
    __nv_bfloat16* As = sm_;                        // [2][128][72]
    __nv_bfloat16* Bs = sm_ + 2 * LG_BUF;           // [2][128][72]
    __shared__ float bsm[128];
    __shared__ float ses[128];

    const int bn = blockIdx.x * 128;
    const int bm = blockIdx.y * 128;
    const int tid = threadIdx.x;
    const int wid = tid >> 5, lane = tid & 31;
    const int warp_m = wid >> 2, warp_n = wid & 3;
    const int g = lane >> 2, tg = lane & 3;

    if (tid < 128) { bsm[tid] = b_fc[bn + tid]; ses[tid] = 0.f; }

    // async load of one 128x64 chunk (A or B) into stage p
    auto loadA = [&](int i, int p) {
        const int k0 = i * 64;
#pragma unroll
        for (int it = 0; it < 4; it++) {
            const int idx = it * 256 + tid;
            const int r = idx >> 3, q = idx & 7;
            int row = bm + r; if (row >= MROWS) row = MROWS - 1;
            uint32_t d = (uint32_t)__cvta_generic_to_shared(As + p * LG_BUF + r * LG_STRIDE + q * 8);
            CPA16(d, g_YSb + (size_t)row * HSZ + k0 + q * 8);
        }
    };
    auto loadB = [&](int i, int p) {
        const int k0 = i * 64;
#pragma unroll
        for (int it = 0; it < 4; it++) {
            const int idx = it * 256 + tid;
            const int r = idx >> 3, q = idx & 7;
            uint32_t d = (uint32_t)__cvta_generic_to_shared(Bs + p * LG_BUF + r * LG_STRIDE + q * 8);
            CPA16(d, g_WFCb + (size_t)(bn + r) * HSZ + k0 + q * 8);
        }
    };

    float acc[4][4][4];
#pragma unroll
    for (int i = 0; i < 4; i++)
#pragma unroll
        for (int j = 0; j < 4; j++)
#pragma unroll
            for (int r = 0; r < 4; r++) acc[i][j][r] = 0.f;

    loadA(0, 0); loadB(0, 0); CPC();

    for (int i = 0; i < 8; i++) {
        const int p = i & 1;
        if (i + 1 < 8) { loadA(i + 1, p ^ 1); loadB(i + 1, p ^ 1); CPC(); CPW(1); }
        else CPW(0);
        __syncthreads();

        const __nv_bfloat16* Ap = As + p * LG_BUF;
        const __nv_bfloat16* Bp = Bs + p * LG_BUF;
#pragma unroll
        for (int kk = 0; kk < 64; kk += 16) {
            uint32_t af[4][4], bfr[4][2];
#pragma unroll
            for (int im = 0; im < 4; im++) {
                int r0 = warp_m * 64 + im * 16;
                af[im][0] = *(const uint32_t*)(Ap + (r0 + g    ) * LG_STRIDE + kk + tg*2    );
                af[im][1] = *(const uint32_t*)(Ap + (r0 + g + 8) * LG_STRIDE + kk + tg*2    );
                af[im][2] = *(const uint32_t*)(Ap + (r0 + g    ) * LG_STRIDE + kk + tg*2 + 8);
                af[im][3] = *(const uint32_t*)(Ap + (r0 + g + 8) * LG_STRIDE + kk + tg*2 + 8);
            }
#pragma unroll
            for (int in_ = 0; in_ < 4; in_++) {
                int c0 = warp_n * 32 + in_ * 8;
                bfr[in_][0] = *(const uint32_t*)(Bp + (c0 + g) * LG_STRIDE + kk + tg*2    );
                bfr[in_][1] = *(const uint32_t*)(Bp + (c0 + g) * LG_STRIDE + kk + tg*2 + 8);
            }
#pragma unroll
            for (int im = 0; im < 4; im++)
#pragma unroll
                for (int in_ = 0; in_ < 4; in_++)
                    mma16816(acc[im][in_], af[im], bfr[in_][0], bfr[in_][1]);
        }
        __syncthreads();
    }

#pragma unroll
    for (int im = 0; im < 4; im++) {
#pragma unroll
        for (int half = 0; half < 2; half++) {
            const int row_l = warp_m * 64 + im * 16 + g + half * 8;
            const int row = bm + row_l;
            if (row >= MROWS) continue;
            float s = 0.f;
#pragma unroll
            for (int in_ = 0; in_ < 4; in_++) {
                const int col_l = warp_n * 32 + in_ * 8 + tg * 2;
                float v0 = acc[im][in_][half*2 + 0] + bsm[col_l];
                float v1 = acc[im][in_][half*2 + 1] + bsm[col_l + 1];
                float2 st; st.x = v0; st.y = v1;
                *(float2*)(out + (size_t)row * VSZ + bn + col_l) = st;
                s += __expf(v0) + __expf(v1);
            }
            atomicAdd(&ses[row_l], s);
        }
    }
    __syncthreads();
    if (tid < 128 && bm + tid < MROWS) atomicAdd(&g_SUMEXP[bm + tid], ses[tid]);
}

// ---------------- fixup: out -= log(sumexp(row)), 4 float4/thread ---------
__global__ void k_fix(float* __restrict__ out)
{
    const size_t base = (size_t)blockIdx.x * 1024 + threadIdx.x;
#pragma unroll
    for (int it = 0; it < 4; it++) {
        const size_t i = base + it * 256;
        const int row = (int)(i / (VSZ / 4));
        const float l = __logf(g_SUMEXP[row]);
        float4 v = ((const float4*)out)[i];
        v.x -= l; v.y -= l; v.z -= l; v.w -= l;
        ((float4*)out)[i] = v;
    }
}

// ---------------- launch ---------------------------------------------------
extern "C" void kernel_launch(void* const* d_in, const int* in_sizes, int n_in,
                              void* d_out, int out_size)
{
    const float* ctx     = (const float*)d_in[0];
    const int*   targets = (const int*)  d_in[1];
    const float* emb     = (const float*)d_in[2];
    const float* W_init  = (const float*)d_in[3];
    const float* b_init  = (const float*)d_in[4];
    const float* Wi0     = (const float*)d_in[5];
    const float* Wh0     = (const float*)d_in[6];
    const float* bi0     = (const float*)d_in[7];
    const float* bh0     = (const float*)d_in[8];
    const float* Wi1     = (const float*)d_in[9];
    const float* Wh1     = (const float*)d_in[10];
    const float* bi1     = (const float*)d_in[11];
    const float* bh1     = (const float*)d_in[12];
    const float* W_fc    = (const float*)d_in[13];
    const float* b_fc    = (const float*)d_in[14];
    float* out = (float*)d_out;

    static int smem_set = 0;
    const int scan_smem = 200 * WB * 2 + 4 * 3 * 32 * 16;   // 208,000 + 6,144 B
    if (!smem_set) {
        cudaFuncSetAttribute(k_scan, cudaFuncAttributeMaxDynamicSharedMemorySize, scan_smem);
        cudaFuncSetAttribute(k_logits, cudaFuncAttributeMaxDynamicSharedMemorySize, LG_SMEM);
        smem_set = 1;
    }

    k_h0<<<128, 128>>>(ctx, W_init, b_init);
    k_cvt_wfc<<<(VSZ * HSZ / 4) / 256, 256>>>(W_fc);
    k_gi0<<<dim3(G3 / 128, (MROWS + 127) / 128), 256>>>(emb, targets, Wi0, bi0);

    k_scan<<<NC, NT, scan_smem>>>(Wh0, bh0, Wi1, Wh1, bi1, bh1);

    k_logits<<<dim3(VSZ / 128, (MROWS + 127) / 128), 256, LG_SMEM>>>(b_fc, out);
    k_fix<<<(int)(((size_t)MROWS * VSZ / 4) / 1024), 256>>>(out);
}

// round 12
// speedup vs baseline: 1.4881x; 1.1858x over previous
#include <cuda_runtime.h>
#include <cuda_bf16.h>
#include <cstdint>

// Shapes
#define VSZ   32000
#define ESZ   512
#define HSZ   512
#define BSZ   64
#define TSZ   65          // sequence steps
#define G3    1536        // 3*H
#define MROWS (BSZ*TSZ)   // 4160 output rows
#define BH    (BSZ*HSZ)

#define NC    64          // scan CTAs (first 64 of the fused grid)
#define NCTA  148         // fused grid (1 CTA/SM, all co-resident)
#define JC    8           // j-columns per scan CTA
#define WB    520         // bf16 row stride (512+8)
#define NT    384         // threads (12 warps)

#define LG_STRIDE 72
#define LG_BUF    (128 * LG_STRIDE)
#define NITEM     (33 * 250)

// ---------------- device scratch (static allocations only) ----------------
__device__ float          g_HA[2 * BH];
__device__ float          g_HB[2 * BH];
__device__ __nv_bfloat16  g_HAb[2 * BH];
__device__ __nv_bfloat16  g_HBb[2 * BH];
__device__ float          g_GI0[TSZ * BSZ * G3];        // 25.6 MB
__device__ __nv_bfloat16  g_WFCb[(size_t)VSZ * HSZ];    // 32.8 MB
__device__ __nv_bfloat16  g_YSb[(size_t)MROWS * HSZ];   // [t*64+b] layout
__device__ float          g_SUMEXP[MROWS];
__device__ unsigned       g_cnt;
__device__ unsigned       g_tick;

__device__ __forceinline__ float sigf(float x) { return 1.f / (1.f + __expf(-x)); }

__device__ __forceinline__ void mma16816(float* c, const uint32_t* a, uint32_t b0, uint32_t b1)
{
    asm volatile(
        "mma.sync.aligned.m16n8k16.row.col.f32.bf16.bf16.f32 "
        "{%0,%1,%2,%3}, {%4,%5,%6,%7}, {%8,%9}, {%0,%1,%2,%3};\n"
        : "+f"(c[0]), "+f"(c[1]), "+f"(c[2]), "+f"(c[3])
        : "r"(a[0]), "r"(a[1]), "r"(a[2]), "r"(a[3]), "r"(b0), "r"(b1));
}

// scan grid barrier: RED arrive + LOAD-based polling (R8 proven)
__device__ __forceinline__ void gbar(unsigned target) {
    __syncthreads();
    if (threadIdx.x == 0) {
        unsigned* p = &g_cnt;
        asm volatile("red.release.gpu.global.add.u32 [%0], 1;" :: "l"(p) : "memory");
        unsigned v;
        do {
            asm volatile("ld.acquire.gpu.global.u32 %0, [%1];" : "=r"(v) : "l"(p) : "memory");
        } while (v < target);
    }
    __syncthreads();
}

#define CPA16(d, s) asm volatile("cp.async.cg.shared.global [%0], [%1], 16;" :: "r"(d), "l"(s) : "memory")
#define CPC()       asm volatile("cp.async.commit_group;" ::: "memory")
#define CPW(n)      asm volatile("cp.async.wait_group %0;" :: "n"(n) : "memory")

// ---------------- h0 + zero counters --------------------------------------
__global__ void k_h0(const float* __restrict__ ctx,
                     const float* __restrict__ W_init,
                     const float* __restrict__ b_init)
{
    const int lb = blockIdx.x;
    const int l = lb >> 6, b = lb & 63;
    const int tid = threadIdx.x;
    __shared__ float cs[HSZ];
    ((float4*)cs)[tid] = ((const float4*)(ctx + (size_t)lb * HSZ))[tid];

    const int gid = blockIdx.x * 128 + tid;
    if (gid < MROWS) g_SUMEXP[gid] = 0.f;
    if (gid == 0) g_cnt = 0;
    if (gid == 1) g_tick = 0;
    __syncthreads();

    float*         hout  = (l == 0) ? g_HA  : g_HB;
    __nv_bfloat16* houtb = (l == 0) ? g_HAb : g_HBb;
#pragma unroll
    for (int jj = 0; jj < 4; jj++) {
        const int j = tid * 4 + jj;
        const float* wr = W_init + (size_t)j * HSZ;
        float acc = 0.f;
        for (int k = 0; k < HSZ; k += 4) {
            float4 w = *(const float4*)(wr + k);
            acc += w.x * cs[k] + w.y * cs[k+1] + w.z * cs[k+2] + w.w * cs[k+3];
        }
        float v = tanhf(acc + b_init[j]);
        hout[b * HSZ + j]  = v;
        houtb[b * HSZ + j] = __float2bfloat16(v);
    }
}

// ---------------- W_fc fp32 -> bf16 ---------------------------------------
__global__ void k_cvt_wfc(const float* __restrict__ wfc)
{
    const size_t i = (size_t)blockIdx.x * 256 + threadIdx.x;
    float4 v = ((const float4*)wfc)[i];
    __nv_bfloat162 lo = __floats2bfloat162_rn(v.x, v.y);
    __nv_bfloat162 hi = __floats2bfloat162_rn(v.z, v.w);
    uint2 o; o.x = *(uint32_t*)&lo; o.y = *(uint32_t*)&hi;
    ((uint2*)g_WFCb)[i] = o;
}

// ---------------- GI0 = gather(emb) @ Wi0^T + bi0 (bf16 mma) --------------
__global__ void k_gi0(const float* __restrict__ emb,
                      const int*   __restrict__ targets,
                      const float* __restrict__ Wi0,
                      const float* __restrict__ bi0)
{
    const int bn = blockIdx.x * 128;
    const int bm = blockIdx.y * 128;
    const int tid = threadIdx.x;
    const int wid = tid >> 5, lane = tid & 31;
    const int warp_m = wid >> 2, warp_n = wid & 3;
    const int g = lane >> 2, tg = lane & 3;

    __shared__ __nv_bfloat16 As[128][72];
    __shared__ __nv_bfloat16 Bs[128][72];
    __shared__ float bsm[128];
    __shared__ int   toks[128];
    if (tid < 128) {
        bsm[tid] = bi0[bn + tid];
        int row = bm + tid; if (row >= MROWS) row = MROWS - 1;
        const int t = row >> 6, b = row & 63;
        toks[tid] = (t == 0) ? 1 : targets[b * TSZ + t - 1];
    }
    __syncthreads();

    float acc[4][4][4];
#pragma unroll
    for (int i = 0; i < 4; i++)
#pragma unroll
        for (int j = 0; j < 4; j++)
#pragma unroll
            for (int r = 0; r < 4; r++) acc[i][j][r] = 0.f;

    for (int k0 = 0; k0 < ESZ; k0 += 64) {
        for (int i = tid; i < 2048; i += 256) {
            const int r = i >> 4, q = i & 15;
            float4 v = *(const float4*)(emb + (size_t)toks[r] * ESZ + k0 + q * 4);
            __nv_bfloat162 p0 = __floats2bfloat162_rn(v.x, v.y);
            __nv_bfloat162 p1 = __floats2bfloat162_rn(v.z, v.w);
            uint2 u; u.x = *(uint32_t*)&p0; u.y = *(uint32_t*)&p1;
            *(uint2*)&As[r][q * 4] = u;
        }
        for (int i = tid; i < 2048; i += 256) {
            const int r = i >> 4, q = i & 15;
            float4 v = *(const float4*)(Wi0 + (size_t)(bn + r) * ESZ + k0 + q * 4);
            __nv_bfloat162 p0 = __floats2bfloat162_rn(v.x, v.y);
            __nv_bfloat162 p1 = __floats2bfloat162_rn(v.z, v.w);
            uint2 u; u.x = *(uint32_t*)&p0; u.y = *(uint32_t*)&p1;
            *(uint2*)&Bs[r][q * 4] = u;
        }
        __syncthreads();
#pragma unroll
        for (int kk = 0; kk < 64; kk += 16) {
            uint32_t af[4][4], bfr[4][2];
#pragma unroll
            for (int im = 0; im < 4; im++) {
                int r0 = warp_m * 64 + im * 16;
                af[im][0] = *(const uint32_t*)&As[r0 + g    ][kk + tg*2    ];
                af[im][1] = *(const uint32_t*)&As[r0 + g + 8][kk + tg*2    ];
                af[im][2] = *(const uint32_t*)&As[r0 + g    ][kk + tg*2 + 8];
                af[im][3] = *(const uint32_t*)&As[r0 + g + 8][kk + tg*2 + 8];
            }
#pragma unroll
            for (int in_ = 0; in_ < 4; in_++) {
                int c0 = warp_n * 32 + in_ * 8;
                bfr[in_][0] = *(const uint32_t*)&Bs[c0 + g][kk + tg*2    ];
                bfr[in_][1] = *(const uint32_t*)&Bs[c0 + g][kk + tg*2 + 8];
            }
#pragma unroll
            for (int im = 0; im < 4; im++)
#pragma unroll
                for (int in_ = 0; in_ < 4; in_++)
                    mma16816(acc[im][in_], af[im], bfr[in_][0], bfr[in_][1]);
        }
        __syncthreads();
    }

#pragma unroll
    for (int im = 0; im < 4; im++) {
#pragma unroll
        for (int half = 0; half < 2; half++) {
            const int row = bm + warp_m * 64 + im * 16 + g + half * 8;
            if (row >= MROWS) continue;
#pragma unroll
            for (int in_ = 0; in_ < 4; in_++) {
                const int col_l = warp_n * 32 + in_ * 8 + tg * 2;
                float2 st;
                st.x = acc[im][in_][half*2 + 0] + bsm[col_l];
                st.y = acc[im][in_][half*2 + 1] + bsm[col_l + 1];
                *(float2*)(g_GI0 + (size_t)row * G3 + bn + col_l) = st;
            }
        }
    }
}

// ---------------- FUSED: persistent scan (CTAs 0-63) + logits consumers ---
__global__ void __launch_bounds__(NT, 1) k_fused(
    const float* __restrict__ Wh0, const float* __restrict__ bh0,
    const float* __restrict__ Wi1, const float* __restrict__ Wh1,
    const float* __restrict__ bi1, const float* __restrict__ bh1,
    const float* __restrict__ b_fc, float* __restrict__ out)
{
    extern __shared__ __nv_bfloat16 smb[];
    __shared__ int s_w;

    const int tid  = threadIdx.x;
    const int wid  = tid >> 5, lane = tid & 31;
    const int g    = lane >> 2, tg = lane & 3;

    // =================== SCAN ROLE (CTAs 0..63) ===================
    if (blockIdx.x < NC) {
        __nv_bfloat16* Wh0s = smb;
        __nv_bfloat16* Wi1s = smb + 24 * WB;
        __nv_bfloat16* Wh1s = smb + 48 * WB;
        __nv_bfloat16* Ax   = smb + 72 * WB;
        __nv_bfloat16* Ah   = Ax  + 64 * WB;
        float4* accS = (float4*)(smb + 200 * WB);

        const int mt   = wid & 3;
        const int mat  = wid >> 2;
        const int m0   = mt * 16;
        const int jb   = blockIdx.x * JC;

        for (int idx = tid; idx < 24 * 128; idx += NT) {
            const int row = idx >> 7, q = idx & 127;
            const int gate = row >> 3, jj = row & 7;
            const size_t grow = (size_t)(gate * HSZ + jb + jj) * HSZ + q * 4;
            const int o = row * WB + q * 4;
            float4 v0 = *(const float4*)(Wh0 + grow);
            float4 v1 = *(const float4*)(Wi1 + grow);
            float4 v2 = *(const float4*)(Wh1 + grow);
            __nv_bfloat162 p0, p1; uint2 u;
            p0 = __floats2bfloat162_rn(v0.x, v0.y); p1 = __floats2bfloat162_rn(v0.z, v0.w);
            u.x = *(uint32_t*)&p0; u.y = *(uint32_t*)&p1; *(uint2*)(Wh0s + o) = u;
            p0 = __floats2bfloat162_rn(v1.x, v1.y); p1 = __floats2bfloat162_rn(v1.z, v1.w);
            u.x = *(uint32_t*)&p0; u.y = *(uint32_t*)&p1; *(uint2*)(Wi1s + o) = u;
            p0 = __floats2bfloat162_rn(v2.x, v2.y); p1 = __floats2bfloat162_rn(v2.z, v2.w);
            u.x = *(uint32_t*)&p0; u.y = *(uint32_t*)&p1; *(uint2*)(Wh1s + o) = u;
        }
        __syncthreads();

        float bg0[3][2], bgi1[3][2], bgh1[3][2];
#pragma unroll
        for (int gi = 0; gi < 3; gi++)
#pragma unroll
            for (int cc = 0; cc < 2; cc++) {
                const int j = gi * HSZ + jb + 2 * tg + cc;
                bg0[gi][cc]  = bh0[j];
                bgi1[gi][cc] = bi1[j];
                bgh1[gi][cc] = bh1[j];
            }

        auto mma3 = [&](const __nv_bfloat16* A, const __nv_bfloat16* W, float acc[3][4]) {
            const __nv_bfloat16* Ar0 = A + (m0 + g) * WB;
            const __nv_bfloat16* Ar1 = Ar0 + 8 * WB;
#pragma unroll
            for (int gi = 0; gi < 3; gi++)
#pragma unroll
                for (int r = 0; r < 4; r++) acc[gi][r] = 0.f;
#pragma unroll
            for (int ks = 0; ks < 32; ks++) {
                const int k = ks * 16;
                uint32_t a[4];
                a[0] = *(const uint32_t*)(Ar0 + k + tg * 2);
                a[1] = *(const uint32_t*)(Ar1 + k + tg * 2);
                a[2] = *(const uint32_t*)(Ar0 + k + 8 + tg * 2);
                a[3] = *(const uint32_t*)(Ar1 + k + 8 + tg * 2);
#pragma unroll
                for (int gi = 0; gi < 3; gi++) {
                    const __nv_bfloat16* br = W + (gi * 8 + g) * WB + k + tg * 2;
                    mma16816(acc[gi], a, *(const uint32_t*)br, *(const uint32_t*)(br + 8));
                }
            }
        };

        auto epi0 = [&](int tt, const float acc0[3][4]) {
            const float* hAin = g_HA + (tt & 1) * BH;
            float* hAout = g_HA + ((tt & 1) ^ 1) * BH;
            __nv_bfloat16* hAbout = g_HAb + ((tt & 1) ^ 1) * BH;
#pragma unroll
            for (int hf = 0; hf < 2; hf++) {
                const int b = m0 + g + 8 * hf;
                const float* gi0p = g_GI0 + ((size_t)tt * BSZ + b) * G3;
#pragma unroll
                for (int cc = 0; cc < 2; cc++) {
                    const int j = jb + 2 * tg + cc;
                    const float r = sigf(__ldg(gi0p + j)          + acc0[0][hf*2+cc] + bg0[0][cc]);
                    const float z = sigf(__ldg(gi0p + HSZ + j)    + acc0[1][hf*2+cc] + bg0[1][cc]);
                    const float n = tanhf(__ldg(gi0p + 2*HSZ + j) + r * (acc0[2][hf*2+cc] + bg0[2][cc]));
                    const float hprev = __ldcg(hAin + (size_t)b * HSZ + j);
                    const float v = (1.f - z) * n + z * hprev;
                    hAout[(size_t)b * HSZ + j]  = v;
                    hAbout[(size_t)b * HSZ + j] = __float2bfloat16(v);
                }
            }
        };

        // prologue: cell0(t=0)
        {
            for (int idx = tid; idx < 64 * 64; idx += NT) {
                const int r = idx >> 6, q = idx & 63;
                *(uint4*)(Ax + r * WB + q * 8) =
                    __ldcg((const uint4*)(g_HAb + (size_t)r * HSZ + q * 8));
            }
            __syncthreads();
            if (mat == 1) {
                float acc0[3][4];
                mma3(Ax, Wh0s, acc0);
                epi0(0, acc0);
            }
        }
        gbar(NC);

        for (int t = 0; t < TSZ; t++) {
            const int cur = t & 1, nxt = cur ^ 1;

            {
                const __nv_bfloat16* srcA = g_HAb + (size_t)nxt * BH;
                const __nv_bfloat16* srcB = g_HBb + (size_t)cur * BH;
                for (int idx = tid; idx < 128 * 64; idx += NT) {
                    const int r = idx >> 6, q = idx & 63;
                    if (r < 64)
                        *(uint4*)(Ax + r * WB + q * 8) =
                            __ldcg((const uint4*)(srcA + (size_t)r * HSZ + q * 8));
                    else
                        *(uint4*)(Ah + (r - 64) * WB + q * 8) =
                            __ldcg((const uint4*)(srcB + (size_t)(r - 64) * HSZ + q * 8));
                }
            }
            __syncthreads();

            float acc[3][4];
            if (mat == 0)      mma3(Ax, Wi1s, acc);
            else if (mat == 1) mma3(Ax, Wh0s, acc);
            else               mma3(Ah, Wh1s, acc);

            if (mat == 0) {
#pragma unroll
                for (int gi = 0; gi < 3; gi++) {
                    float4 v; v.x = acc[gi][0]; v.y = acc[gi][1]; v.z = acc[gi][2]; v.w = acc[gi][3];
                    accS[((wid & 3) * 3 + gi) * 32 + lane] = v;
                }
            }
            __syncthreads();

            if (mat == 2) {
                const float* hBin = g_HB + (size_t)cur * BH;
                float* hBout = g_HB + (size_t)nxt * BH;
                __nv_bfloat16* hBbout = g_HBb + (size_t)nxt * BH;
                float accx[3][4];
#pragma unroll
                for (int gi = 0; gi < 3; gi++) {
                    float4 v = accS[((wid & 3) * 3 + gi) * 32 + lane];
                    accx[gi][0] = v.x; accx[gi][1] = v.y; accx[gi][2] = v.z; accx[gi][3] = v.w;
                }
#pragma unroll
                for (int hf = 0; hf < 2; hf++) {
                    const int b = m0 + g + 8 * hf;
#pragma unroll
                    for (int cc = 0; cc < 2; cc++) {
                        const int j = jb + 2 * tg + cc;
                        const float r = sigf(accx[0][hf*2+cc] + bgi1[0][cc] + acc[0][hf*2+cc] + bgh1[0][cc]);
                        const float z = sigf(accx[1][hf*2+cc] + bgi1[1][cc] + acc[1][hf*2+cc] + bgh1[1][cc]);
                        const float n = tanhf(accx[2][hf*2+cc] + bgi1[2][cc]
                                              + r * (acc[2][hf*2+cc] + bgh1[2][cc]));
                        const float hprev = __ldcg(hBin + (size_t)b * HSZ + j);
                        const float v = (1.f - z) * n + z * hprev;
                        hBout[(size_t)b * HSZ + j]  = v;
                        hBbout[(size_t)b * HSZ + j] = __float2bfloat16(v);
                        g_YSb[((size_t)t * BSZ + b) * HSZ + j] = __float2bfloat16(v);  // [t*64+b]
                    }
                }
            } else if (mat == 1 && t < TSZ - 1) {
                epi0(t + 1, acc);
            }

            if (t < TSZ - 1) gbar((unsigned)(t + 2) * NC);
        }

        // publish final step (t=64) writes
        __syncthreads();
        if (tid == 0)
            asm volatile("red.release.gpu.global.add.u32 [%0], 1;" :: "l"(&g_cnt) : "memory");
    }

    // =================== CONSUMER ROLE (all CTAs end here) ===================
    {
        __nv_bfloat16* As = smb;                       // [2][128][72]
        __nv_bfloat16* Bs = smb + 2 * LG_BUF;
        float* bsm = (float*)(Bs + 2 * LG_BUF);        // 128
        float* ses = bsm + 128;                        // 128

        const int warp_m = wid >> 2, warp_n = wid & 3; // valid for wid<8
        const bool active = (tid < 256);

        for (;;) {
            if (tid == 0) s_w = (int)atomicAdd(&g_tick, 1u);
            __syncthreads();
            const int w = s_w;
            if (w >= NITEM) break;
            const int mu = w / 250, nb = w % 250;
            const int bm = mu * 128, bn = nb * 128;
            const int need_t = (2 * mu + 1 < TSZ - 1) ? (2 * mu + 1) : (TSZ - 1);
            const unsigned wait_val = (unsigned)(need_t + 2) * NC;

            if (tid == 0) {
                unsigned v;
                for (;;) {
                    asm volatile("ld.acquire.gpu.global.u32 %0, [%1];" : "=r"(v) : "l"(&g_cnt) : "memory");
                    if (v >= wait_val) break;
                    __nanosleep(256);
                }
            }
            if (tid < 128) { bsm[tid] = b_fc[bn + tid]; ses[tid] = 0.f; }
            __syncthreads();

            float acc[4][4][4];
#pragma unroll
            for (int i = 0; i < 4; i++)
#pragma unroll
                for (int j = 0; j < 4; j++)
#pragma unroll
                    for (int r = 0; r < 4; r++) acc[i][j][r] = 0.f;

            // prime stage 0
            if (active) {
#pragma unroll
                for (int it = 0; it < 4; it++) {
                    const int idx = it * 256 + tid;
                    const int r = idx >> 3, q = idx & 7;
                    int row = bm + r; if (row >= MROWS) row = MROWS - 1;
                    uint32_t d = (uint32_t)__cvta_generic_to_shared(As + r * LG_STRIDE + q * 8);
                    CPA16(d, g_YSb + (size_t)row * HSZ + q * 8);
                    uint32_t d2 = (uint32_t)__cvta_generic_to_shared(Bs + r * LG_STRIDE + q * 8);
                    CPA16(d2, g_WFCb + (size_t)(bn + r) * HSZ + q * 8);
                }
            }
            CPC();

            for (int i = 0; i < 8; i++) {
                const int p = i & 1;
                if (i + 1 < 8) {
                    if (active) {
                        const int k0 = (i + 1) * 64, pn = p ^ 1;
#pragma unroll
                        for (int it = 0; it < 4; it++) {
                            const int idx = it * 256 + tid;
                            const int r = idx >> 3, q = idx & 7;
                            int row = bm + r; if (row >= MROWS) row = MROWS - 1;
                            uint32_t d = (uint32_t)__cvta_generic_to_shared(As + pn * LG_BUF + r * LG_STRIDE + q * 8);
                            CPA16(d, g_YSb + (size_t)row * HSZ + k0 + q * 8);
                            uint32_t d2 = (uint32_t)__cvta_generic_to_shared(Bs + pn * LG_BUF + r * LG_STRIDE + q * 8);
                            CPA16(d2, g_WFCb + (size_t)(bn + r) * HSZ + k0 + q * 8);
                        }
                    }
                    CPC(); CPW(1);
                } else CPW(0);
                __syncthreads();

                if (active) {
                    const __nv_bfloat16* Ap = As + p * LG_BUF;
                    const __nv_bfloat16* Bp = Bs + p * LG_BUF;
#pragma unroll
                    for (int kk = 0; kk < 64; kk += 16) {
                        uint32_t af[4][4], bfr[4][2];
#pragma unroll
                        for (int im = 0; im < 4; im++) {
                            int r0 = warp_m * 64 + im * 16;
                            af[im][0] = *(const uint32_t*)(Ap + (r0 + g    ) * LG_STRIDE + kk + tg*2    );
                            af[im][1] = *(const uint32_t*)(Ap + (r0 + g + 8) * LG_STRIDE + kk + tg*2    );
                            af[im][2] = *(const uint32_t*)(Ap + (r0 + g    ) * LG_STRIDE + kk + tg*2 + 8);
                            af[im][3] = *(const uint32_t*)(Ap + (r0 + g + 8) * LG_STRIDE + kk + tg*2 + 8);
                        }
#pragma unroll
                        for (int in_ = 0; in_ < 4; in_++) {
                            int c0 = warp_n * 32 + in_ * 8;
                            bfr[in_][0] = *(const uint32_t*)(Bp + (c0 + g) * LG_STRIDE + kk + tg*2    );
                            bfr[in_][1] = *(const uint32_t*)(Bp + (c0 + g) * LG_STRIDE + kk + tg*2 + 8);
                        }
#pragma unroll
                        for (int im = 0; im < 4; im++)
#pragma unroll
                            for (int in_ = 0; in_ < 4; in_++)
                                mma16816(acc[im][in_], af[im], bfr[in_][0], bfr[in_][1]);
                    }
                }
                __syncthreads();
            }

            if (active) {
#pragma unroll
                for (int im = 0; im < 4; im++) {
#pragma unroll
                    for (int half = 0; half < 2; half++) {
                        const int row_l = warp_m * 64 + im * 16 + g + half * 8;
                        const int r_ys = bm + row_l;
                        if (r_ys >= MROWS) continue;
                        const int orow = (r_ys & 63) * TSZ + (r_ys >> 6);
                        float s = 0.f;
#pragma unroll
                        for (int in_ = 0; in_ < 4; in_++) {
                            const int col_l = warp_n * 32 + in_ * 8 + tg * 2;
                            float v0 = acc[im][in_][half*2 + 0] + bsm[col_l];
                            float v1 = acc[im][in_][half*2 + 1] + bsm[col_l + 1];
                            float2 st; st.x = v0; st.y = v1;
                            *(float2*)(out + (size_t)orow * VSZ + bn + col_l) = st;
                            s += __expf(v0) + __expf(v1);
                        }
                        atomicAdd(&ses[row_l], s);
                    }
                }
            }
            __syncthreads();
            if (tid < 128) {
                const int r_ys = bm + tid;
                if (r_ys < MROWS) {
                    const int orow = (r_ys & 63) * TSZ + (r_ys >> 6);
                    atomicAdd(&g_SUMEXP[orow], ses[tid]);
                }
            }
            __syncthreads();
        }
    }
}

// ---------------- fixup: out -= log(sumexp(row)), 4 float4/thread ---------
__global__ void k_fix(float* __restrict__ out)
{
    const size_t base = (size_t)blockIdx.x * 1024 + threadIdx.x;
#pragma unroll
    for (int it = 0; it < 4; it++) {
        const size_t i = base + it * 256;
        const int row = (int)(i / (VSZ / 4));
        const float l = __logf(g_SUMEXP[row]);
        float4 v = ((const float4*)out)[i];
        v.x -= l; v.y -= l; v.z -= l; v.w -= l;
        ((float4*)out)[i] = v;
    }
}

// ---------------- launch ---------------------------------------------------
extern "C" void kernel_launch(void* const* d_in, const int* in_sizes, int n_in,
                              void* d_out, int out_size)
{
    const float* ctx     = (const float*)d_in[0];
    const int*   targets = (const int*)  d_in[1];
    const float* emb     = (const float*)d_in[2];
    const float* W_init  = (const float*)d_in[3];
    const float* b_init  = (const float*)d_in[4];
    const float* Wi0     = (const float*)d_in[5];
    const float* Wh0     = (const float*)d_in[6];
    const float* bi0     = (const float*)d_in[7];
    const float* bh0     = (const float*)d_in[8];
    const float* Wi1     = (const float*)d_in[9];
    const float* Wh1     = (const float*)d_in[10];
    const float* bi1     = (const float*)d_in[11];
    const float* bh1     = (const float*)d_in[12];
    const float* W_fc    = (const float*)d_in[13];
    const float* b_fc    = (const float*)d_in[14];
    float* out = (float*)d_out;

    static int smem_set = 0;
    const int fused_smem = 200 * WB * 2 + 4 * 3 * 32 * 16;   // 214,144 B
    if (!smem_set) {
        cudaFuncSetAttribute(k_fused, cudaFuncAttributeMaxDynamicSharedMemorySize, fused_smem);
        smem_set = 1;
    }

    k_h0<<<128, 128>>>(ctx, W_init, b_init);
    k_cvt_wfc<<<(VSZ * HSZ / 4) / 256, 256>>>(W_fc);
    k_gi0<<<dim3(G3 / 128, (MROWS + 127) / 128), 256>>>(emb, targets, Wi0, bi0);

    k_fused<<<NCTA, NT, fused_smem>>>(Wh0, bh0, Wi1, Wh1, bi1, bh1, b_fc, out);

    k_fix<<<(int)(((size_t)MROWS * VSZ / 4) / 1024), 256>>>(out);
}